// round 10
// baseline (speedup 1.0000x reference)
#include <cuda_runtime.h>
#include <math.h>
#include <stdint.h>

#define Ntok 1024
#define Dm   2048
#define Fm   5632
#define Em   8
#define Rm   16
#define LSCALE 2.0f
#define NBALL (2*Fm + 256)   // 11520
#define FCH  256
#define NCH  (Fm / FCH)      // 22
#define NPERSIST 592

// ---------------- device scratch ----------------
__device__ float g_bapart[(size_t)2 * Ntok * NBALL];    // GEMM1 partials (a, b)
__device__ float g_s    [(size_t)Ntok * 2 * Fm];
__device__ float g_l2p  [(size_t)Ntok * 2 * NCH * 16];
__device__ float g_wpart[(size_t)8 * Ntok * Dm];        // GEMM2 partials (4 a + 4 b)
__device__ int   g_topi [Ntok * 2];
__device__ float g_topw [Ntok * 2];
__device__ uint32_t g_elist[Em * Ntok];
__device__ int   g_ecnt[Em];
// int8 operand buffers: A-side layout [q1|q2], B-side [p2|p1]
__device__ __align__(256) int8_t g_xq   [(size_t)Ntok  * 2 * Dm];
__device__ __align__(256) int8_t g_wallq[(size_t)NBALL * 2 * Dm];
__device__ __align__(256) int8_t g_w2q  [(size_t)Dm    * 2 * Fm];
__device__ __align__(256) int8_t g_smq  [(size_t)Ntok  * 2 * Fm];
__device__ float g_sxa [Ntok];
__device__ float g_swall[NBALL];
__device__ float g_ssm [Ntok];
__device__ float g_sw2 [Dm];

// ---------------- PTX helpers ----------------
__device__ __forceinline__ uint32_t s2u(const void* p) {
    uint32_t a;
    asm("{ .reg .u64 t; cvta.to.shared.u64 t, %1; cvt.u32.u64 %0, t; }" : "=r"(a) : "l"(p));
    return a;
}
#define CPA16(d, s) asm volatile("cp.async.cg.shared.global [%0], [%1], 16;" :: "r"(d), "l"(s))
#define LDSM4(R0,R1,R2,R3,addr) asm volatile( \
    "ldmatrix.sync.aligned.m8n8.x4.shared.b16 {%0,%1,%2,%3}, [%4];" \
    : "=r"(R0),"=r"(R1),"=r"(R2),"=r"(R3) : "r"(addr))
#define MMAI8(c, a, b0, b1) asm volatile( \
    "mma.sync.aligned.m16n8k32.row.col.s32.s8.s8.s32 " \
    "{%0,%1,%2,%3}, {%4,%5,%6,%7}, {%8,%9}, {%0,%1,%2,%3};" \
    : "+r"((c)[0]),"+r"((c)[1]),"+r"((c)[2]),"+r"((c)[3]) \
    : "r"((a)[0]),"r"((a)[1]),"r"((a)[2]),"r"((a)[3]), "r"(b0),"r"(b1))

// ---------------- block row max -> scale ----------------
__device__ __forceinline__ float block_rowmax(float mx, float* wmx) {
    #pragma unroll
    for (int o = 16; o; o >>= 1) mx = fmaxf(mx, __shfl_xor_sync(0xffffffffu, mx, o));
    int tid = threadIdx.x;
    if ((tid & 31) == 0) wmx[tid >> 5] = mx;
    __syncthreads();
    float m2 = wmx[0];
    #pragma unroll
    for (int w = 1; w < 8; w++) m2 = fmaxf(m2, wmx[w]);
    return fmaxf(m2, 1e-30f);
}

__device__ __forceinline__ char4 q4(float4 v, float inv, float s) {
    float q1x = rintf(v.x * inv), q1y = rintf(v.y * inv);
    float q1z = rintf(v.z * inv), q1w = rintf(v.w * inv);
    char4 c; c.x = (char)(int)q1x; c.y = (char)(int)q1y; c.z = (char)(int)q1z; c.w = (char)(int)q1w;
    return c;
}
__device__ __forceinline__ char4 q4r(float4 v, float inv, float s) {
    float i2 = inv * 256.f;
    float rx = v.x - rintf(v.x * inv) * s, ry = v.y - rintf(v.y * inv) * s;
    float rz = v.z - rintf(v.z * inv) * s, rw = v.w - rintf(v.w * inv) * s;
    float qx = fminf(fmaxf(rintf(rx * i2), -127.f), 127.f);
    float qy = fminf(fmaxf(rintf(ry * i2), -127.f), 127.f);
    float qz = fminf(fmaxf(rintf(rz * i2), -127.f), 127.f);
    float qw = fminf(fmaxf(rintf(rw * i2), -127.f), 127.f);
    char4 c; c.x = (char)(int)qx; c.y = (char)(int)qy; c.z = (char)(int)qz; c.w = (char)(int)qw;
    return c;
}

// ---------------- generic row quantizer ----------------
__device__ __forceinline__ void quant_row_core(const float* __restrict__ p, int8_t* __restrict__ dst,
                                               float* __restrict__ scale, int row, int K, int rev,
                                               float* wmx) {
    int tid = threadIdx.x;
    const float4* p4 = (const float4*)p;
    int K4 = K >> 2;
    float mx = 0.f;
    for (int i = tid; i < K4; i += 256) {
        float4 v = p4[i];
        mx = fmaxf(mx, fmaxf(fmaxf(fabsf(v.x), fabsf(v.y)), fmaxf(fabsf(v.z), fabsf(v.w))));
    }
    float m2 = block_rowmax(mx, wmx);
    float s = m2 / 127.f, inv = 127.f / m2;
    if (tid == 0) scale[row] = s;
    char4* d1 = (char4*)(dst + (size_t)row * 2 * K + (rev ? K : 0));  // primary q1/p1
    char4* d2 = (char4*)(dst + (size_t)row * 2 * K + (rev ? 0 : K));  // residual q2/p2
    for (int i = tid; i < K4; i += 256) {
        float4 v = p4[i];
        d1[i] = q4(v, inv, s);
        d2[i] = q4r(v, inv, s);
    }
}

__global__ void quant_x(const float* __restrict__ x) {
    __shared__ float wmx[8];
    quant_row_core(x + (size_t)blockIdx.x * Dm, g_xq, g_sxa, blockIdx.x, Dm, 0, wmx);
}

__global__ void quant_wall(const float* __restrict__ W1, const float* __restrict__ W3,
                           const float* __restrict__ A1, const float* __restrict__ A3) {
    __shared__ float wmx[8];
    int row = blockIdx.x;
    const float* p;
    if (row < Fm) p = W1 + (size_t)row * Dm;
    else if (row < 2 * Fm) p = W3 + (size_t)(row - Fm) * Dm;
    else {
        int r2 = row - 2 * Fm;
        int e = r2 >> 5, rr = r2 & 31;
        p = (rr < 16) ? A1 + ((size_t)e * 16 + rr) * Dm
                      : A3 + ((size_t)e * 16 + (rr - 16)) * Dm;
    }
    quant_row_core(p, g_wallq, g_swall, row, Dm, 1, wmx);
}

__global__ void quant_w2(const float* __restrict__ W2) {
    __shared__ float wmx[8];
    quant_row_core(W2 + (size_t)blockIdx.x * Fm, g_w2q, g_sw2, blockIdx.x, Fm, 1, wmx);
}

// ---------------- int8 GEMM: 128x128 tile, warp 64x32, 64B/kt, 4-stage (R7 pipeline) ----------------
#define NSTAGE      4
#define STAGE_BYTES 10240
#define BBUF_OFF    (NSTAGE * STAGE_BYTES)
#define GEMM_SMEM   (2 * BBUF_OFF)

__global__ void __launch_bounds__(256, 2)
gemm_i8(const int8_t* __restrict__ Ag, const int8_t* __restrict__ Bg,
        int Astride, int Bstride,
        const float* __restrict__ sA, const float* __restrict__ sB,
        int Nn, int gridM, int gridN, int ntA, int ntTot,
        int KperA, int boffA, float* CA, float wsA,
        int KperB, int boffB, float* CB, float wsB) {
    extern __shared__ char smraw[];
    const uint32_t sb = s2u(smraw);
    const int tid = threadIdx.x;
    const int lane = tid & 31, wid = tid >> 5;
    const int wm = wid & 1, wn = wid >> 1;

    const int r = tid >> 1, half = tid & 1;
    const uint32_t dA = sb + r * 80 + half * 32;
    const uint32_t dB = sb + BBUF_OFF + r * 80 + half * 32;

    const uint32_t lrow = (uint32_t)(lane & 15);
    const uint32_t lcolb = (uint32_t)(lane >> 4) * 16;
    const uint32_t aLd = sb + (wm * 64 + lrow) * 80 + lcolb;
    const uint32_t bLd = sb + BBUF_OFF + (wn * 32 + lrow) * 80 + lcolb;

    for (int t = blockIdx.x; t < ntTot; t += gridDim.x) {
        int tt = t;
        int Kper, boff; float* C; float ws;
        if (tt < ntA) { Kper = KperA; boff = boffA; C = CA; ws = wsA; }
        else { tt -= ntA; Kper = KperB; boff = boffB; C = CB; ws = wsB; }
        int tm = tt % gridM;
        int rem = tt / gridM;
        int tn = rem % gridN;
        int z  = rem / gridN;
        const int bm = tm * 128, bn = tn * 128;
        const int koff = z * Kper;
        float* Cz = C + (size_t)z * (size_t)(gridM * 128) * Nn;
        const int nk = Kper >> 6;

        const int8_t* gA = Ag + (size_t)(bm + r) * Astride + koff + half * 32;
        const int8_t* gB = Bg + (size_t)(bn + r) * Bstride + boff + koff + half * 32;

        int acc[4][4][4];
        #pragma unroll
        for (int i = 0; i < 4; i++)
            #pragma unroll
            for (int j = 0; j < 4; j++)
                #pragma unroll
                for (int q = 0; q < 4; q++) acc[i][j][q] = 0;

        #pragma unroll
        for (int s = 0; s < NSTAGE - 1; s++) {
            const int8_t* a = gA + s * 64;
            const int8_t* b = gB + s * 64;
            uint32_t so = (uint32_t)s * STAGE_BYTES;
            CPA16(dA + so, a); CPA16(dA + so + 16, a + 16);
            CPA16(dB + so, b); CPA16(dB + so + 16, b + 16);
            asm volatile("cp.async.commit_group;" ::: "memory");
        }

        for (int kt = 0; kt < nk; kt++) {
            asm volatile("cp.async.wait_group 2;" ::: "memory");
            __syncthreads();

            const uint32_t so = (uint32_t)(kt & (NSTAGE - 1)) * STAGE_BYTES;
            #pragma unroll
            for (int ks = 0; ks < 2; ks++) {
                uint32_t Ar[4][4], Br[2][4];
                #pragma unroll
                for (int mt = 0; mt < 4; mt++)
                    LDSM4(Ar[mt][0], Ar[mt][1], Ar[mt][2], Ar[mt][3],
                          aLd + so + mt * 1280 + ks * 32);
                #pragma unroll
                for (int p = 0; p < 2; p++)
                    LDSM4(Br[p][0], Br[p][1], Br[p][2], Br[p][3],
                          bLd + so + p * 1280 + ks * 32);
                #pragma unroll
                for (int mt = 0; mt < 4; mt++)
                    #pragma unroll
                    for (int nt = 0; nt < 4; nt++) {
                        uint32_t b0 = Br[nt >> 1][nt & 1];
                        uint32_t b1 = Br[nt >> 1][2 + (nt & 1)];
                        MMAI8(acc[mt][nt], Ar[mt], b0, b1);
                    }
            }

            int ls = kt + NSTAGE - 1;
            if (ls < nk) {
                uint32_t so2 = (uint32_t)(ls & (NSTAGE - 1)) * STAGE_BYTES;
                const int8_t* a = gA + (size_t)ls * 64;
                const int8_t* b = gB + (size_t)ls * 64;
                CPA16(dA + so2, a); CPA16(dA + so2 + 16, a + 16);
                CPA16(dB + so2, b); CPA16(dB + so2 + 16, b + 16);
            }
            asm volatile("cp.async.commit_group;" ::: "memory");
        }

        const int g = lane >> 2, t4 = lane & 3;
        #pragma unroll
        for (int mt = 0; mt < 4; mt++) {
            int row = bm + wm * 64 + mt * 16 + g;
            float sa0 = sA[row] * ws, sa1 = sA[row + 8] * ws;
            #pragma unroll
            for (int nt = 0; nt < 4; nt++) {
                int col = bn + wn * 32 + nt * 8 + 2 * t4;
                float sb0 = sB[col], sb1 = sB[col + 1];
                *(float2*)(Cz + (size_t)row * Nn + col) =
                    make_float2(sa0 * sb0 * (float)acc[mt][nt][0], sa0 * sb1 * (float)acc[mt][nt][1]);
                *(float2*)(Cz + (size_t)(row + 8) * Nn + col) =
                    make_float2(sa1 * sb0 * (float)acc[mt][nt][2], sa1 * sb1 * (float)acc[mt][nt][3]);
            }
        }
        asm volatile("cp.async.wait_group 0;" ::: "memory");
        __syncthreads();
    }
}

// ---------------- router ----------------
__global__ void gate_kernel(const float* __restrict__ x,
                            const float* __restrict__ gw,
                            float* __restrict__ logits_out) {
    int n = blockIdx.x;
    int tid = threadIdx.x;
    __shared__ float sx[Dm];
    for (int i = tid; i < Dm; i += 256) sx[i] = x[(size_t)n * Dm + i];
    __syncthreads();
    int w = tid >> 5, lane = tid & 31;
    const float* g = gw + (size_t)w * Dm;
    float sum = 0.f;
    for (int d = lane; d < Dm; d += 32) sum += sx[d] * g[d];
    #pragma unroll
    for (int o = 16; o; o >>= 1) sum += __shfl_down_sync(0xffffffffu, sum, o);
    __shared__ float slog[Em];
    if (lane == 0) slog[w] = sum;
    __syncthreads();
    if (tid == 0) {
        float mx = slog[0];
        #pragma unroll
        for (int e = 1; e < Em; e++) mx = fmaxf(mx, slog[e]);
        float p[Em], Z = 0.f;
        #pragma unroll
        for (int e = 0; e < Em; e++) { p[e] = expf(slog[e] - mx); Z += p[e]; }
        #pragma unroll
        for (int e = 0; e < Em; e++) p[e] /= Z;
        int i0 = 0;
        #pragma unroll
        for (int e = 1; e < Em; e++) if (p[e] > p[i0]) i0 = e;
        int i1 = (i0 == 0) ? 1 : 0;
        #pragma unroll
        for (int e = 0; e < Em; e++) { if (e == i0 || e == i1) continue; if (p[e] > p[i1]) i1 = e; }
        float w0 = p[i0], w1 = p[i1], s = w0 + w1;
        g_topi[n * 2 + 0] = i0; g_topi[n * 2 + 1] = i1;
        g_topw[n * 2 + 0] = w0 / s; g_topw[n * 2 + 1] = w1 / s;
        #pragma unroll
        for (int e = 0; e < Em; e++) logits_out[(size_t)n * Em + e] = slog[e];
    }
}

// ---------------- deterministic per-expert token lists ----------------
__global__ void build_list_kernel() {
    int e = blockIdx.x;
    int tid = threadIdx.x;
    __shared__ int wcnt[8];
    __shared__ int base;
    if (tid == 0) base = 0;
    __syncthreads();
    for (int t0 = 0; t0 < Ntok; t0 += 256) {
        int n = t0 + tid;
        int k = -1;
        if (g_topi[2 * n] == e) k = 0;
        else if (g_topi[2 * n + 1] == e) k = 1;
        unsigned b = __ballot_sync(0xffffffffu, k >= 0);
        int lane = tid & 31, w = tid >> 5;
        if (lane == 0) wcnt[w] = __popc(b);
        __syncthreads();
        int off = base;
        for (int ww = 0; ww < w; ww++) off += wcnt[ww];
        off += __popc(b & ((1u << lane) - 1));
        if (k >= 0) g_elist[e * Ntok + off] = (uint32_t)n | ((uint32_t)k << 16);
        __syncthreads();
        if (tid == 0) {
            int tot = 0;
            for (int ww = 0; ww < 8; ww++) tot += wcnt[ww];
            base += tot;
        }
        __syncthreads();
    }
    if (tid == 0) g_ecnt[e] = base;
}

// ---------------- expert-major SwiGLU, warp-per-token (merges GEMM1 a+b partials) ----------------
#define EFFN_SMEM (48 * FCH * 4)
__global__ void __launch_bounds__(256)
expert_ffn(const float* __restrict__ B1, const float* __restrict__ B3,
           const float* __restrict__ A2) {
    int e = blockIdx.x, ch = blockIdx.y;
    int f0 = ch * FCH;
    extern __shared__ float sm[];
    float* B1s = sm;
    float* B3s = sm + 16 * FCH;
    float* A2s = sm + 32 * FCH;
    int tid = threadIdx.x, lane = tid & 31, wid = tid >> 5;

    {
        const float4* p1 = (const float4*)(B1 + ((size_t)e * Fm + f0 + tid) * 16);
        const float4* p3 = (const float4*)(B3 + ((size_t)e * Fm + f0 + tid) * 16);
        #pragma unroll
        for (int q = 0; q < 4; q++) {
            float4 v1 = p1[q], v3 = p3[q];
            B1s[(4*q+0)*FCH + tid] = v1.x; B1s[(4*q+1)*FCH + tid] = v1.y;
            B1s[(4*q+2)*FCH + tid] = v1.z; B1s[(4*q+3)*FCH + tid] = v1.w;
            B3s[(4*q+0)*FCH + tid] = v3.x; B3s[(4*q+1)*FCH + tid] = v3.y;
            B3s[(4*q+2)*FCH + tid] = v3.z; B3s[(4*q+3)*FCH + tid] = v3.w;
        }
        #pragma unroll
        for (int rr = 0; rr < 16; rr++)
            A2s[rr * FCH + tid] = A2[((size_t)e * 16 + rr) * Fm + f0 + tid];
    }
    __syncthreads();

    const float* bp0 = g_bapart;
    const float* bp1 = g_bapart + (size_t)Ntok * NBALL;

    int cnt = g_ecnt[e];
    for (int i = wid; i < cnt; i += 8) {
        uint32_t pk = g_elist[e * Ntok + i];
        int n = pk & 0xFFFF, k = (int)(pk >> 16);
        size_t roff = (size_t)n * NBALL;
        float l13 = bp0[roff + 2 * Fm + e * 32 + lane] + bp1[roff + 2 * Fm + e * 32 + lane];
        float l1r[16], l3r[16];
        #pragma unroll
        for (int rr = 0; rr < 16; rr++) {
            l1r[rr] = __shfl_sync(0xffffffffu, l13, rr);
            l3r[rr] = __shfl_sync(0xffffffffu, l13, 16 + rr);
        }
        float l2a[16];
        #pragma unroll
        for (int rr = 0; rr < 16; rr++) l2a[rr] = 0.f;

        float* srow = g_s + ((size_t)n * 2 + k) * Fm;
        #pragma unroll
        for (int fi = 0; fi < 8; fi++) {
            int fl = fi * 32 + lane;
            float b1v = bp0[roff + f0 + fl]      + bp1[roff + f0 + fl];
            float b3v = bp0[roff + Fm + f0 + fl] + bp1[roff + Fm + f0 + fl];
            float h1 = 0.f, h3 = 0.f;
            #pragma unroll
            for (int rr = 0; rr < 16; rr++) {
                h1 = fmaf(l1r[rr], B1s[rr * FCH + fl], h1);
                h3 = fmaf(l3r[rr], B3s[rr * FCH + fl], h3);
            }
            h1 = fmaf(LSCALE, h1, b1v);
            h3 = fmaf(LSCALE, h3, b3v);
            float sig = 1.f / (1.f + expf(-h1));
            float s = h1 * sig * h3;
            srow[f0 + fl] = s;
            #pragma unroll
            for (int rr = 0; rr < 16; rr++)
                l2a[rr] = fmaf(s, A2s[rr * FCH + fl], l2a[rr]);
        }
        #pragma unroll
        for (int rr = 0; rr < 16; rr++) {
            float v = l2a[rr];
            #pragma unroll
            for (int o = 16; o; o >>= 1) v += __shfl_down_sync(0xffffffffu, v, o);
            if (lane == 0)
                g_l2p[(((size_t)n * 2 + k) * NCH + ch) * 16 + rr] = v;
        }
    }
}

// ---------------- mix + int8 quantize of smix ----------------
__global__ void mix_quant() {
    int n = blockIdx.x;
    int tid = threadIdx.x;
    __shared__ float buf[Fm];
    __shared__ float wmx[8];
    float w0 = g_topw[2 * n], w1 = g_topw[2 * n + 1];
    const float4* s0p = (const float4*)(g_s + ((size_t)n * 2) * Fm);
    const float4* s1p = (const float4*)(g_s + ((size_t)n * 2 + 1) * Fm);
    float mx = 0.f;
    for (int i = tid; i < Fm / 4; i += 256) {
        float4 a = s0p[i], b = s1p[i];
        float4 m;
        m.x = w0 * a.x + w1 * b.x;
        m.y = w0 * a.y + w1 * b.y;
        m.z = w0 * a.z + w1 * b.z;
        m.w = w0 * a.w + w1 * b.w;
        ((float4*)buf)[i] = m;
        mx = fmaxf(mx, fmaxf(fmaxf(fabsf(m.x), fabsf(m.y)), fmaxf(fabsf(m.z), fabsf(m.w))));
    }
    float m2 = block_rowmax(mx, wmx);
    float s = m2 / 127.f, inv = 127.f / m2;
    if (tid == 0) g_ssm[n] = s;
    __syncthreads();
    char4* d1 = (char4*)(g_smq + (size_t)n * 2 * Fm);        // q1
    char4* d2 = (char4*)(g_smq + (size_t)n * 2 * Fm + Fm);   // q2
    for (int i = tid; i < Fm / 4; i += 256) {
        float4 v = ((const float4*)buf)[i];
        d1[i] = q4(v, inv, s);
        d2[i] = q4r(v, inv, s);
    }
}

// ---------------- output: 8-partial merge + LoRA ----------------
__global__ void lora_out_kernel(const float* __restrict__ B2, float* __restrict__ out) {
    int n = blockIdx.y;
    int d = blockIdx.x * 256 + threadIdx.x;
    __shared__ float sl2[32];
    __shared__ int se[2];
    if (threadIdx.x < 32) {
        int k = threadIdx.x >> 4, rr = threadIdx.x & 15;
        float v = 0.f;
        #pragma unroll
        for (int ch = 0; ch < NCH; ch++)
            v += g_l2p[(((size_t)n * 2 + k) * NCH + ch) * 16 + rr];
        sl2[threadIdx.x] = v * g_topw[n * 2 + k] * LSCALE;
    }
    if (threadIdx.x < 2) se[threadIdx.x] = g_topi[n * 2 + threadIdx.x];
    __syncthreads();
    float acc = 0.f;
    #pragma unroll
    for (int z = 0; z < 8; z++)
        acc += g_wpart[(size_t)z * Ntok * Dm + (size_t)n * Dm + d];
    #pragma unroll
    for (int k = 0; k < 2; k++) {
        int e = se[k];
        const float4* bp = (const float4*)(B2 + ((size_t)e * Dm + d) * Rm);
        #pragma unroll
        for (int q = 0; q < 4; q++) {
            float4 v = bp[q];
            acc += sl2[k*16+4*q+0]*v.x + sl2[k*16+4*q+1]*v.y + sl2[k*16+4*q+2]*v.z + sl2[k*16+4*q+3]*v.w;
        }
    }
    out[(size_t)n * Dm + d] = acc;
}

// --------------------------------- launch --------------------------------
extern "C" void kernel_launch(void* const* d_in, const int* in_sizes, int n_in,
                              void* d_out, int out_size) {
    const float* x      = (const float*)d_in[0];
    const float* gate_w = (const float*)d_in[1];
    const float* W1     = (const float*)d_in[2];
    const float* W3     = (const float*)d_in[3];
    const float* W2     = (const float*)d_in[4];
    const float* A1     = (const float*)d_in[5];
    const float* B1     = (const float*)d_in[6];
    const float* A3     = (const float*)d_in[7];
    const float* B3     = (const float*)d_in[8];
    const float* A2     = (const float*)d_in[9];
    const float* B2     = (const float*)d_in[10];

    float* out    = (float*)d_out;
    float* logits = (float*)d_out + (size_t)Ntok * Dm;

    float *bapart, *wpart, *sxa, *swall, *ssm, *sw2;
    int8_t *xq, *wallq, *w2q, *smq;
    cudaGetSymbolAddress((void**)&bapart, g_bapart);
    cudaGetSymbolAddress((void**)&wpart,  g_wpart);
    cudaGetSymbolAddress((void**)&xq,     g_xq);
    cudaGetSymbolAddress((void**)&wallq,  g_wallq);
    cudaGetSymbolAddress((void**)&w2q,    g_w2q);
    cudaGetSymbolAddress((void**)&smq,    g_smq);
    cudaGetSymbolAddress((void**)&sxa,    g_sxa);
    cudaGetSymbolAddress((void**)&swall,  g_swall);
    cudaGetSymbolAddress((void**)&ssm,    g_ssm);
    cudaGetSymbolAddress((void**)&sw2,    g_sw2);

    cudaFuncSetAttribute(gemm_i8, cudaFuncAttributeMaxDynamicSharedMemorySize, GEMM_SMEM);
    cudaFuncSetAttribute(expert_ffn, cudaFuncAttributeMaxDynamicSharedMemorySize, EFFN_SMEM);

    // quantize operands
    quant_x<<<Ntok, 256>>>(x);
    quant_wall<<<NBALL, 256>>>(W1, W3, A1, A3);
    quant_w2<<<Dm, 256>>>(W2);

    // router + expert lists
    gate_kernel<<<Ntok, 256>>>(x, gate_w, logits);
    build_list_kernel<<<Em, 256>>>();

    // phase 1: [x@W1 | x@W3 | x@A13] — a (q1·p1, ws=1) + b ([q1·p2|q2·p1], ws=1/256)
    gemm_i8<<<NPERSIST, 256, GEMM_SMEM>>>(
        xq, wallq, 2 * Dm, 2 * Dm, sxa, swall,
        NBALL, Ntok / 128, NBALL / 128,
        720, 1440,
        /*a*/ Dm,     Dm, bapart,                         1.f,
        /*b*/ 2 * Dm, 0,  bapart + (size_t)Ntok * NBALL,  1.f / 256.f);

    // expert-major SwiGLU + l2 partials
    {
        dim3 grid(Em, NCH);
        expert_ffn<<<grid, 256, EFFN_SMEM>>>(B1, B3, A2);
    }
    // mix + quantize
    mix_quant<<<Ntok, 256>>>();

    // phase 2: smix @ W2^T — a split-K4 (ws=1) + b split-K4 (ws=1/256)
    gemm_i8<<<NPERSIST, 256, GEMM_SMEM>>>(
        smq, w2q, 2 * Fm, 2 * Fm, ssm, sw2,
        Dm, Ntok / 128, Dm / 128,
        512, 1024,
        /*a*/ Fm / 4,     Fm, wpart,                        1.f,
        /*b*/ 2 * Fm / 4, 0,  wpart + (size_t)4 * Ntok * Dm, 1.f / 256.f);

    // merge 8 partials + output LoRA
    {
        dim3 grid(Dm / 256, Ntok);
        lora_out_kernel<<<grid, 256>>>(B2, out);
    }
}

// round 11
// speedup vs baseline: 1.7076x; 1.7076x over previous
#include <cuda_runtime.h>
#include <cuda_bf16.h>
#include <math.h>
#include <stdint.h>

#define Ntok 1024
#define Dm   2048
#define Fm   5632
#define Em   8
#define Rm   16
#define LSCALE 2.0f
#define NBALL (2*Fm + 256)   // 11520
#define FCH  256
#define NCH  (Fm / FCH)      // 22
#define ZW2  4
#define KV2  (3*Fm)          // virtual K for GEMM2 = 16896
#define KPER_W2 (KV2 / ZW2)  // 4224
#define NPERSIST 592

// ---------------- device scratch ----------------
__device__ float g_baseall[(size_t)Ntok * NBALL];
__device__ float g_s    [(size_t)Ntok * 2 * Fm];
__device__ float g_l2p  [(size_t)Ntok * 2 * NCH * 16];
__device__ float g_wpart[(size_t)ZW2 * Ntok * Dm];
__device__ int   g_topi [Ntok * 2];
__device__ float g_topw [Ntok * 2];
__device__ uint32_t g_elist[Em * Ntok];
__device__ int   g_ecnt[Em];
// 2-term bf16 operands: row layout [hi (K) | lo (K)]
__device__ __align__(256) __nv_bfloat16 g_xc2  [(size_t)Ntok  * 2 * Dm];
__device__ __align__(256) __nv_bfloat16 g_wall2[(size_t)NBALL * 2 * Dm];
__device__ __align__(256) __nv_bfloat16 g_w22  [(size_t)Dm    * 2 * Fm];
__device__ __align__(256) __nv_bfloat16 g_sm2  [(size_t)Ntok  * 2 * Fm];

// ---------------- PTX helpers ----------------
__device__ __forceinline__ uint32_t s2u(const void* p) {
    uint32_t a;
    asm("{ .reg .u64 t; cvta.to.shared.u64 t, %1; cvt.u32.u64 %0, t; }" : "=r"(a) : "l"(p));
    return a;
}
#define CPA16(d, s) asm volatile("cp.async.cg.shared.global [%0], [%1], 16;" :: "r"(d), "l"(s))
#define LDSM4(R0,R1,R2,R3,addr) asm volatile( \
    "ldmatrix.sync.aligned.m8n8.x4.shared.b16 {%0,%1,%2,%3}, [%4];" \
    : "=r"(R0),"=r"(R1),"=r"(R2),"=r"(R3) : "r"(addr))
#define MMA16816(c, a, b0, b1) asm volatile( \
    "mma.sync.aligned.m16n8k16.row.col.f32.bf16.bf16.f32 " \
    "{%0,%1,%2,%3}, {%4,%5,%6,%7}, {%8,%9}, {%0,%1,%2,%3};" \
    : "+f"((c)[0]),"+f"((c)[1]),"+f"((c)[2]),"+f"((c)[3]) \
    : "r"((a)[0]),"r"((a)[1]),"r"((a)[2]),"r"((a)[3]), "r"(b0),"r"(b1))

// pack 8 fp32 -> (hi uint4, lo uint4) bf16
__device__ __forceinline__ void split8(const float* p, uint4& H, uint4& L) {
    float v[8];
    *(float4*)&v[0] = *(const float4*)p;
    *(float4*)&v[4] = *(const float4*)(p + 4);
    uint32_t h[4], l[4];
    #pragma unroll
    for (int i = 0; i < 4; i++) {
        __nv_bfloat16 h0 = __float2bfloat16(v[2*i]);
        __nv_bfloat16 h1 = __float2bfloat16(v[2*i+1]);
        __nv_bfloat16 l0 = __float2bfloat16(v[2*i]   - __bfloat162float(h0));
        __nv_bfloat16 l1 = __float2bfloat16(v[2*i+1] - __bfloat162float(h1));
        __nv_bfloat162 hp; hp.x = h0; hp.y = h1;
        __nv_bfloat162 lp; lp.x = l0; lp.y = l1;
        h[i] = *(uint32_t*)&hp;
        l[i] = *(uint32_t*)&lp;
    }
    H = make_uint4(h[0], h[1], h[2], h[3]);
    L = make_uint4(l[0], l[1], l[2], l[3]);
}

// ---------------- fp32 -> [hi|lo] split (2K layout) ----------------
__global__ void split2_kernel(const float* __restrict__ src, __nv_bfloat16* __restrict__ dst,
                              int K, int total8) {
    int t = blockIdx.x * 256 + threadIdx.x;
    if (t >= total8) return;
    size_t idx = (size_t)t * 8;
    int row = (int)(idx / K);
    int col = (int)(idx - (size_t)row * K);
    uint4 H, L;
    split8(src + idx, H, L);
    __nv_bfloat16* base = dst + (size_t)row * 2 * K + col;
    *(uint4*)base = H;
    *(uint4*)(base + K) = L;
}

__global__ void split2_a13_kernel(const float* __restrict__ A1, const float* __restrict__ A3,
                                  __nv_bfloat16* __restrict__ dst) {
    int t = blockIdx.x * 256 + threadIdx.x;
    size_t idx = (size_t)t * 8;
    int row = (int)(idx / Dm);
    int col = (int)(idx - (size_t)row * Dm);
    int e = row >> 5, rr = row & 31;
    const float* src = (rr < 16) ? (A1 + ((size_t)e * 16 + rr) * Dm)
                                 : (A3 + ((size_t)e * 16 + (rr - 16)) * Dm);
    uint4 H, L;
    split8(src + col, H, L);
    __nv_bfloat16* base = dst + (size_t)row * 2 * Dm + col;
    *(uint4*)base = H;
    *(uint4*)(base + Dm) = L;
}

// ======== persistent HMMA GEMM (R7 core) with virtual-3K region walk ========
// regions over virtual K = 3*Kelem: 0:(Ahi,Bhi) 1:(Ahi,Blo) 2:(Alo,Bhi)
#define NSTAGE      4
#define STAGE_BYTES 10240
#define BBUF_OFF    (NSTAGE * STAGE_BYTES)
#define GEMM_SMEM   (2 * BBUF_OFF)

__device__ __forceinline__ void region_offs(int vk, int Kelem, int& ao, int& bo, int& kk) {
    if (vk >= 2 * Kelem)      { ao = Kelem; bo = 0;     kk = vk - 2 * Kelem; }
    else if (vk >= Kelem)     { ao = 0;     bo = Kelem; kk = vk - Kelem; }
    else                      { ao = 0;     bo = 0;     kk = vk; }
}

__global__ void __launch_bounds__(256, 2)
gemm_mma(const __nv_bfloat16* __restrict__ Ag, const __nv_bfloat16* __restrict__ Bg,
         float* __restrict__ Cg, int Nn, int Kelem, int Kper,
         int gridM, int gridN, int ntiles) {
    extern __shared__ char smraw[];
    const uint32_t sb = s2u(smraw);
    const int tid = threadIdx.x;
    const int lane = tid & 31, wid = tid >> 5;
    const int wm = wid & 1, wn = wid >> 1;
    const int Astride = 2 * Kelem;
    const int nk = Kper >> 5;

    const int r = tid >> 1, half = tid & 1;
    const uint32_t dA = sb + r * 80 + half * 32;
    const uint32_t dB = sb + BBUF_OFF + r * 80 + half * 32;

    const uint32_t lrow = (uint32_t)(lane & 15);
    const uint32_t lcolb = (uint32_t)(lane >> 4) * 16;
    const uint32_t aLd = sb + (wm * 64 + lrow) * 80 + lcolb;
    const uint32_t bLd = sb + BBUF_OFF + (wn * 32 + lrow) * 80 + lcolb;

    for (int t = blockIdx.x; t < ntiles; t += gridDim.x) {
        int tm = t % gridM;
        int rem = t / gridM;
        int tn = rem % gridN;
        int z  = rem / gridN;
        const int bm = tm * 128, bn = tn * 128;
        const int koff = z * Kper;
        float* Cz = Cg + (size_t)z * (size_t)(gridM * 128) * Nn;

        const __nv_bfloat16* gA = Ag + (size_t)(bm + r) * Astride + half * 16;
        const __nv_bfloat16* gB = Bg + (size_t)(bn + r) * Astride + half * 16;

        float acc[4][4][4];
        #pragma unroll
        for (int i = 0; i < 4; i++)
            #pragma unroll
            for (int j = 0; j < 4; j++)
                #pragma unroll
                for (int q = 0; q < 4; q++) acc[i][j][q] = 0.f;

        #pragma unroll
        for (int s = 0; s < NSTAGE - 1; s++) {
            int ao, bo, kk;
            region_offs(koff + s * 32, Kelem, ao, bo, kk);
            const __nv_bfloat16* a = gA + ao + kk;
            const __nv_bfloat16* b = gB + bo + kk;
            uint32_t so = (uint32_t)s * STAGE_BYTES;
            CPA16(dA + so, a); CPA16(dA + so + 16, a + 8);
            CPA16(dB + so, b); CPA16(dB + so + 16, b + 8);
            asm volatile("cp.async.commit_group;" ::: "memory");
        }

        for (int kt = 0; kt < nk; kt++) {
            asm volatile("cp.async.wait_group 2;" ::: "memory");
            __syncthreads();

            const uint32_t so = (uint32_t)(kt & (NSTAGE - 1)) * STAGE_BYTES;
            #pragma unroll
            for (int ks = 0; ks < 2; ks++) {
                uint32_t Ar[4][4], Br[2][4];
                #pragma unroll
                for (int mt = 0; mt < 4; mt++)
                    LDSM4(Ar[mt][0], Ar[mt][1], Ar[mt][2], Ar[mt][3],
                          aLd + so + mt * 1280 + ks * 32);
                #pragma unroll
                for (int p = 0; p < 2; p++)
                    LDSM4(Br[p][0], Br[p][1], Br[p][2], Br[p][3],
                          bLd + so + p * 1280 + ks * 32);
                #pragma unroll
                for (int mt = 0; mt < 4; mt++)
                    #pragma unroll
                    for (int nt = 0; nt < 4; nt++) {
                        uint32_t b0 = Br[nt >> 1][nt & 1];
                        uint32_t b1 = Br[nt >> 1][2 + (nt & 1)];
                        MMA16816(acc[mt][nt], Ar[mt], b0, b1);
                    }
            }

            int ls = kt + NSTAGE - 1;
            if (ls < nk) {
                int ao, bo, kk;
                region_offs(koff + ls * 32, Kelem, ao, bo, kk);
                uint32_t so2 = (uint32_t)(ls & (NSTAGE - 1)) * STAGE_BYTES;
                const __nv_bfloat16* a = gA + ao + kk;
                const __nv_bfloat16* b = gB + bo + kk;
                CPA16(dA + so2, a); CPA16(dA + so2 + 16, a + 8);
                CPA16(dB + so2, b); CPA16(dB + so2 + 16, b + 8);
            }
            asm volatile("cp.async.commit_group;" ::: "memory");
        }

        const int g = lane >> 2, t4 = lane & 3;
        #pragma unroll
        for (int mt = 0; mt < 4; mt++) {
            int row = bm + wm * 64 + mt * 16 + g;
            #pragma unroll
            for (int nt = 0; nt < 4; nt++) {
                int col = bn + wn * 32 + nt * 8 + 2 * t4;
                *(float2*)(Cz + (size_t)row * Nn + col)       = make_float2(acc[mt][nt][0], acc[mt][nt][1]);
                *(float2*)(Cz + (size_t)(row + 8) * Nn + col) = make_float2(acc[mt][nt][2], acc[mt][nt][3]);
            }
        }
        asm volatile("cp.async.wait_group 0;" ::: "memory");
        __syncthreads();
    }
}

// ---------------- router ----------------
__global__ void gate_kernel(const float* __restrict__ x,
                            const float* __restrict__ gw,
                            float* __restrict__ logits_out) {
    int n = blockIdx.x;
    int tid = threadIdx.x;
    __shared__ float sx[Dm];
    for (int i = tid; i < Dm; i += 256) sx[i] = x[(size_t)n * Dm + i];
    __syncthreads();
    int w = tid >> 5, lane = tid & 31;
    const float* g = gw + (size_t)w * Dm;
    float sum = 0.f;
    for (int d = lane; d < Dm; d += 32) sum += sx[d] * g[d];
    #pragma unroll
    for (int o = 16; o; o >>= 1) sum += __shfl_down_sync(0xffffffffu, sum, o);
    __shared__ float slog[Em];
    if (lane == 0) slog[w] = sum;
    __syncthreads();
    if (tid == 0) {
        float mx = slog[0];
        #pragma unroll
        for (int e = 1; e < Em; e++) mx = fmaxf(mx, slog[e]);
        float p[Em], Z = 0.f;
        #pragma unroll
        for (int e = 0; e < Em; e++) { p[e] = expf(slog[e] - mx); Z += p[e]; }
        #pragma unroll
        for (int e = 0; e < Em; e++) p[e] /= Z;
        int i0 = 0;
        #pragma unroll
        for (int e = 1; e < Em; e++) if (p[e] > p[i0]) i0 = e;
        int i1 = (i0 == 0) ? 1 : 0;
        #pragma unroll
        for (int e = 0; e < Em; e++) { if (e == i0 || e == i1) continue; if (p[e] > p[i1]) i1 = e; }
        float w0 = p[i0], w1 = p[i1], s = w0 + w1;
        g_topi[n * 2 + 0] = i0; g_topi[n * 2 + 1] = i1;
        g_topw[n * 2 + 0] = w0 / s; g_topw[n * 2 + 1] = w1 / s;
        #pragma unroll
        for (int e = 0; e < Em; e++) logits_out[(size_t)n * Em + e] = slog[e];
    }
}

// ---------------- deterministic per-expert token lists ----------------
__global__ void build_list_kernel() {
    int e = blockIdx.x;
    int tid = threadIdx.x;
    __shared__ int wcnt[8];
    __shared__ int base;
    if (tid == 0) base = 0;
    __syncthreads();
    for (int t0 = 0; t0 < Ntok; t0 += 256) {
        int n = t0 + tid;
        int k = -1;
        if (g_topi[2 * n] == e) k = 0;
        else if (g_topi[2 * n + 1] == e) k = 1;
        unsigned b = __ballot_sync(0xffffffffu, k >= 0);
        int lane = tid & 31, w = tid >> 5;
        if (lane == 0) wcnt[w] = __popc(b);
        __syncthreads();
        int off = base;
        for (int ww = 0; ww < w; ww++) off += wcnt[ww];
        off += __popc(b & ((1u << lane) - 1));
        if (k >= 0) g_elist[e * Ntok + off] = (uint32_t)n | ((uint32_t)k << 16);
        __syncthreads();
        if (tid == 0) {
            int tot = 0;
            for (int ww = 0; ww < 8; ww++) tot += wcnt[ww];
            base += tot;
        }
        __syncthreads();
    }
    if (tid == 0) g_ecnt[e] = base;
}

// ---------------- expert-major SwiGLU, warp-per-token, float4-vectorized ----------------
#define EFFN_SMEM (48 * FCH * 4)
__global__ void __launch_bounds__(256)
expert_ffn(const float* __restrict__ B1, const float* __restrict__ B3,
           const float* __restrict__ A2) {
    int e = blockIdx.x, ch = blockIdx.y;
    int f0 = ch * FCH;
    extern __shared__ float sm[];
    float* B1s = sm;                 // [rr][FCH]
    float* B3s = sm + 16 * FCH;
    float* A2s = sm + 32 * FCH;
    int tid = threadIdx.x, lane = tid & 31, wid = tid >> 5;

    {
        const float4* p1 = (const float4*)(B1 + ((size_t)e * Fm + f0 + tid) * 16);
        const float4* p3 = (const float4*)(B3 + ((size_t)e * Fm + f0 + tid) * 16);
        #pragma unroll
        for (int q = 0; q < 4; q++) {
            float4 v1 = p1[q], v3 = p3[q];
            B1s[(4*q+0)*FCH + tid] = v1.x; B1s[(4*q+1)*FCH + tid] = v1.y;
            B1s[(4*q+2)*FCH + tid] = v1.z; B1s[(4*q+3)*FCH + tid] = v1.w;
            B3s[(4*q+0)*FCH + tid] = v3.x; B3s[(4*q+1)*FCH + tid] = v3.y;
            B3s[(4*q+2)*FCH + tid] = v3.z; B3s[(4*q+3)*FCH + tid] = v3.w;
        }
        #pragma unroll
        for (int rr = 0; rr < 16; rr++)
            A2s[rr * FCH + tid] = A2[((size_t)e * 16 + rr) * Fm + f0 + tid];
    }
    __syncthreads();

    int cnt = g_ecnt[e];
    for (int i = wid; i < cnt; i += 8) {
        uint32_t pk = g_elist[e * Ntok + i];
        int n = pk & 0xFFFF, k = (int)(pk >> 16);
        size_t roff = (size_t)n * NBALL;
        float l13 = g_baseall[roff + 2 * Fm + e * 32 + lane];
        float l1r[16], l3r[16];
        #pragma unroll
        for (int rr = 0; rr < 16; rr++) {
            l1r[rr] = __shfl_sync(0xffffffffu, l13, rr);
            l3r[rr] = __shfl_sync(0xffffffffu, l13, 16 + rr);
        }
        float l2a[16];
        #pragma unroll
        for (int rr = 0; rr < 16; rr++) l2a[rr] = 0.f;

        const float* brow = g_baseall + roff;
        float* srow = g_s + ((size_t)n * 2 + k) * Fm;
        #pragma unroll
        for (int fi = 0; fi < 2; fi++) {
            int fb = fi * 128 + lane * 4;        // 4 consecutive f per lane
            float4 b1v = *(const float4*)(brow + f0 + fb);
            float4 b3v = *(const float4*)(brow + Fm + f0 + fb);
            float h1[4] = {0.f, 0.f, 0.f, 0.f};
            float h3[4] = {0.f, 0.f, 0.f, 0.f};
            #pragma unroll
            for (int rr = 0; rr < 16; rr++) {
                float4 w1 = *(const float4*)&B1s[rr * FCH + fb];
                float4 w3 = *(const float4*)&B3s[rr * FCH + fb];
                h1[0] = fmaf(l1r[rr], w1.x, h1[0]); h1[1] = fmaf(l1r[rr], w1.y, h1[1]);
                h1[2] = fmaf(l1r[rr], w1.z, h1[2]); h1[3] = fmaf(l1r[rr], w1.w, h1[3]);
                h3[0] = fmaf(l3r[rr], w3.x, h3[0]); h3[1] = fmaf(l3r[rr], w3.y, h3[1]);
                h3[2] = fmaf(l3r[rr], w3.z, h3[2]); h3[3] = fmaf(l3r[rr], w3.w, h3[3]);
            }
            float s4[4];
            float bb1[4] = {b1v.x, b1v.y, b1v.z, b1v.w};
            float bb3[4] = {b3v.x, b3v.y, b3v.z, b3v.w};
            #pragma unroll
            for (int j = 0; j < 4; j++) {
                float hh1 = fmaf(LSCALE, h1[j], bb1[j]);
                float hh3 = fmaf(LSCALE, h3[j], bb3[j]);
                float sig = 1.f / (1.f + expf(-hh1));
                s4[j] = hh1 * sig * hh3;
            }
            *(float4*)(srow + f0 + fb) = make_float4(s4[0], s4[1], s4[2], s4[3]);
            #pragma unroll
            for (int rr = 0; rr < 16; rr++) {
                float4 a2 = *(const float4*)&A2s[rr * FCH + fb];
                l2a[rr] = fmaf(s4[0], a2.x, fmaf(s4[1], a2.y, fmaf(s4[2], a2.z, fmaf(s4[3], a2.w, l2a[rr]))));
            }
        }
        #pragma unroll
        for (int rr = 0; rr < 16; rr++) {
            float v = l2a[rr];
            #pragma unroll
            for (int o = 16; o; o >>= 1) v += __shfl_down_sync(0xffffffffu, v, o);
            if (lane == 0)
                g_l2p[(((size_t)n * 2 + k) * NCH + ch) * 16 + rr] = v;
        }
    }
}

// ---------------- mix + bf16 [hi|lo] split of smix ----------------
__global__ void mix_split2_kernel() {
    int t = blockIdx.x * 256 + threadIdx.x;
    size_t idx = (size_t)t * 8;
    int n = (int)(idx / Fm);
    int f = (int)(idx - (size_t)n * Fm);
    float w0 = g_topw[2 * n], w1 = g_topw[2 * n + 1];
    const float* s0p = g_s + ((size_t)n * 2) * Fm + f;
    const float* s1p = g_s + ((size_t)n * 2 + 1) * Fm + f;
    float m[8];
    #pragma unroll
    for (int q = 0; q < 2; q++) {
        float4 a = *(const float4*)(s0p + 4 * q);
        float4 b = *(const float4*)(s1p + 4 * q);
        m[4*q+0] = w0 * a.x + w1 * b.x;
        m[4*q+1] = w0 * a.y + w1 * b.y;
        m[4*q+2] = w0 * a.z + w1 * b.z;
        m[4*q+3] = w0 * a.w + w1 * b.w;
    }
    uint4 H, L;
    split8(m, H, L);
    __nv_bfloat16* base = g_sm2 + (size_t)n * 2 * Fm + f;
    *(uint4*)base = H;
    *(uint4*)(base + Fm) = L;
}

// ---------------- output: split-K merge + LoRA ----------------
__global__ void lora_out_kernel(const float* __restrict__ B2, float* __restrict__ out) {
    int n = blockIdx.y;
    int d = blockIdx.x * 256 + threadIdx.x;
    __shared__ float sl2[32];
    __shared__ int se[2];
    if (threadIdx.x < 32) {
        int k = threadIdx.x >> 4, rr = threadIdx.x & 15;
        float v = 0.f;
        #pragma unroll
        for (int ch = 0; ch < NCH; ch++)
            v += g_l2p[(((size_t)n * 2 + k) * NCH + ch) * 16 + rr];
        sl2[threadIdx.x] = v * g_topw[n * 2 + k] * LSCALE;
    }
    if (threadIdx.x < 2) se[threadIdx.x] = g_topi[n * 2 + threadIdx.x];
    __syncthreads();
    float acc = 0.f;
    #pragma unroll
    for (int z = 0; z < ZW2; z++)
        acc += g_wpart[(size_t)z * Ntok * Dm + (size_t)n * Dm + d];
    #pragma unroll
    for (int k = 0; k < 2; k++) {
        int e = se[k];
        const float4* bp = (const float4*)(B2 + ((size_t)e * Dm + d) * Rm);
        #pragma unroll
        for (int q = 0; q < 4; q++) {
            float4 v = bp[q];
            acc += sl2[k*16+4*q+0]*v.x + sl2[k*16+4*q+1]*v.y + sl2[k*16+4*q+2]*v.z + sl2[k*16+4*q+3]*v.w;
        }
    }
    out[(size_t)n * Dm + d] = acc;
}

// --------------------------------- launch --------------------------------
extern "C" void kernel_launch(void* const* d_in, const int* in_sizes, int n_in,
                              void* d_out, int out_size) {
    const float* x      = (const float*)d_in[0];
    const float* gate_w = (const float*)d_in[1];
    const float* W1     = (const float*)d_in[2];
    const float* W3     = (const float*)d_in[3];
    const float* W2     = (const float*)d_in[4];
    const float* A1     = (const float*)d_in[5];
    const float* B1     = (const float*)d_in[6];
    const float* A3     = (const float*)d_in[7];
    const float* B3     = (const float*)d_in[8];
    const float* A2     = (const float*)d_in[9];
    const float* B2     = (const float*)d_in[10];

    float* out    = (float*)d_out;
    float* logits = (float*)d_out + (size_t)Ntok * Dm;

    float *baseall, *wpart;
    __nv_bfloat16 *xc2, *wall2, *w22, *sm2;
    cudaGetSymbolAddress((void**)&baseall, g_baseall);
    cudaGetSymbolAddress((void**)&wpart, g_wpart);
    cudaGetSymbolAddress((void**)&xc2,   g_xc2);
    cudaGetSymbolAddress((void**)&wall2, g_wall2);
    cudaGetSymbolAddress((void**)&w22,   g_w22);
    cudaGetSymbolAddress((void**)&sm2,   g_sm2);

    cudaFuncSetAttribute(gemm_mma, cudaFuncAttributeMaxDynamicSharedMemorySize, GEMM_SMEM);
    cudaFuncSetAttribute(expert_ffn, cudaFuncAttributeMaxDynamicSharedMemorySize, EFFN_SMEM);

    // splits ([hi|lo] 2K layout)
    split2_kernel<<<Ntok * Dm / 8 / 256, 256>>>(x, xc2, Dm, Ntok * Dm / 8);
    split2_kernel<<<Fm * Dm / 8 / 256, 256>>>(W1, wall2, Dm, Fm * Dm / 8);
    split2_kernel<<<Fm * Dm / 8 / 256, 256>>>(W3, wall2 + (size_t)Fm * 2 * Dm, Dm, Fm * Dm / 8);
    split2_a13_kernel<<<256 * Dm / 8 / 256, 256>>>(A1, A3, wall2 + (size_t)2 * Fm * 2 * Dm);
    split2_kernel<<<Dm * Fm / 8 / 256, 256>>>(W2, w22, Fm, Dm * Fm / 8);

    // router + expert lists
    gate_kernel<<<Ntok, 256>>>(x, gate_w, logits);
    build_list_kernel<<<Em, 256>>>();

    // fused base GEMM: [x@W1 | x@W3 | x@A13] — persistent, virtual K = 3*Dm
    {
        int ntiles = (Ntok / 128) * (NBALL / 128);      // 720
        gemm_mma<<<NPERSIST, 256, GEMM_SMEM>>>(xc2, wall2, baseall,
                                               NBALL, Dm, 3 * Dm,
                                               Ntok / 128, NBALL / 128, ntiles);
    }
    // expert-major SwiGLU + l2 partials
    {
        dim3 grid(Em, NCH);
        expert_ffn<<<grid, 256, EFFN_SMEM>>>(B1, B3, A2);
    }
    // mix + split
    mix_split2_kernel<<<Ntok * Fm / 8 / 256, 256>>>();
    // down-projection GEMM, split-K=4 over virtual K = 3*Fm
    {
        int ntiles = (Ntok / 128) * (Dm / 128) * ZW2;   // 512
        gemm_mma<<<ntiles, 256, GEMM_SMEM>>>(sm2, w22, wpart,
                                             Dm, Fm, KPER_W2,
                                             Ntok / 128, Dm / 128, ntiles);
    }
    // merge partials + output LoRA
    {
        dim3 grid(Dm / 256, Ntok);
        lora_out_kernel<<<grid, 256>>>(B2, out);
    }
}

// round 12
// speedup vs baseline: 1.8552x; 1.0864x over previous
#include <cuda_runtime.h>
#include <cuda_bf16.h>
#include <math.h>
#include <stdint.h>

#define Ntok 1024
#define Dm   2048
#define Fm   5632
#define Em   8
#define Rm   16
#define LSCALE 2.0f
#define K3D  (3*Dm)    // 6144
#define K3F  (3*Fm)    // 16896
#define NBALL (2*Fm + 256)   // 11520
#define FCH  256
#define NCH  (Fm / FCH)      // 22
#define ZW2  4
#define KPER_W2 (K3F / ZW2)  // 4224
#define NPERSIST 592

// ---------------- device scratch ----------------
__device__ float g_baseall[(size_t)Ntok * NBALL];
__device__ float g_s    [(size_t)Ntok * 2 * Fm];
__device__ float g_l2p  [(size_t)Ntok * 2 * NCH * 16];
__device__ float g_wpart[(size_t)ZW2 * Ntok * Dm];
__device__ int   g_topi [Ntok * 2];
__device__ float g_topw [Ntok * 2];
__device__ uint32_t g_elist[Em * Ntok];
__device__ int   g_ecnt[Em];
__device__ __align__(256) __nv_bfloat16 g_xcat [(size_t)Ntok  * K3D];
__device__ __align__(256) __nv_bfloat16 g_wallc[(size_t)NBALL * K3D];
__device__ __align__(256) __nv_bfloat16 g_w2c  [(size_t)Dm    * K3F];
__device__ __align__(256) __nv_bfloat16 g_smc  [(size_t)Ntok  * K3F];

// ---------------- PTX helpers ----------------
__device__ __forceinline__ uint32_t s2u(const void* p) {
    uint32_t a;
    asm("{ .reg .u64 t; cvta.to.shared.u64 t, %1; cvt.u32.u64 %0, t; }" : "=r"(a) : "l"(p));
    return a;
}
#define CPA16(d, s) asm volatile("cp.async.cg.shared.global [%0], [%1], 16;" :: "r"(d), "l"(s))
#define LDSM4(R0,R1,R2,R3,addr) asm volatile( \
    "ldmatrix.sync.aligned.m8n8.x4.shared.b16 {%0,%1,%2,%3}, [%4];" \
    : "=r"(R0),"=r"(R1),"=r"(R2),"=r"(R3) : "r"(addr))
#define MMA16816(c, a, b0, b1) asm volatile( \
    "mma.sync.aligned.m16n8k16.row.col.f32.bf16.bf16.f32 " \
    "{%0,%1,%2,%3}, {%4,%5,%6,%7}, {%8,%9}, {%0,%1,%2,%3};" \
    : "+f"((c)[0]),"+f"((c)[1]),"+f"((c)[2]),"+f"((c)[3]) \
    : "r"((a)[0]),"r"((a)[1]),"r"((a)[2]),"r"((a)[3]), "r"(b0),"r"(b1))

// pack 8 fp32 -> (hi uint4, lo uint4) bf16
__device__ __forceinline__ void split8(const float* p, uint4& H, uint4& L) {
    float v[8];
    *(float4*)&v[0] = *(const float4*)p;
    *(float4*)&v[4] = *(const float4*)(p + 4);
    uint32_t h[4], l[4];
    #pragma unroll
    for (int i = 0; i < 4; i++) {
        __nv_bfloat16 h0 = __float2bfloat16(v[2*i]);
        __nv_bfloat16 h1 = __float2bfloat16(v[2*i+1]);
        __nv_bfloat16 l0 = __float2bfloat16(v[2*i]   - __bfloat162float(h0));
        __nv_bfloat16 l1 = __float2bfloat16(v[2*i+1] - __bfloat162float(h1));
        __nv_bfloat162 hp; hp.x = h0; hp.y = h1;
        __nv_bfloat162 lp; lp.x = l0; lp.y = l1;
        h[i] = *(uint32_t*)&hp;
        l[i] = *(uint32_t*)&lp;
    }
    H = make_uint4(h[0], h[1], h[2], h[3]);
    L = make_uint4(l[0], l[1], l[2], l[3]);
}

// ---------------- fp32 -> [hi|hi|lo] (A) or [hi|lo|hi] (B) split ----------------
__global__ void split_kernel(const float* __restrict__ src, __nv_bfloat16* __restrict__ dst,
                             int K, int total8, int bmode) {
    int t = blockIdx.x * 256 + threadIdx.x;
    if (t >= total8) return;
    size_t idx = (size_t)t * 8;
    int row = (int)(idx / K);
    int col = (int)(idx - (size_t)row * K);
    uint4 H, L;
    split8(src + idx, H, L);
    __nv_bfloat16* base = dst + (size_t)row * 3 * K + col;
    *(uint4*)base = H;
    if (bmode) { *(uint4*)(base + K) = L; *(uint4*)(base + 2 * K) = H; }
    else       { *(uint4*)(base + K) = H; *(uint4*)(base + 2 * K) = L; }
}

__global__ void split_a13_kernel(const float* __restrict__ A1, const float* __restrict__ A3,
                                 __nv_bfloat16* __restrict__ dst) {
    int t = blockIdx.x * 256 + threadIdx.x;
    size_t idx = (size_t)t * 8;
    int row = (int)(idx / Dm);
    int col = (int)(idx - (size_t)row * Dm);
    int e = row >> 5, rr = row & 31;
    const float* src = (rr < 16) ? (A1 + ((size_t)e * 16 + rr) * Dm)
                                 : (A3 + ((size_t)e * 16 + (rr - 16)) * Dm);
    uint4 H, L;
    split8(src + col, H, L);
    __nv_bfloat16* base = dst + (size_t)row * K3D + col;
    *(uint4*)base = H;
    *(uint4*)(base + Dm) = L;
    *(uint4*)(base + 2 * Dm) = H;
}

// ======== persistent HMMA GEMM (R7 config): 128x128, warp 64x32, BK=32, 4-stage ========
#define NSTAGE      4
#define STAGE_BYTES 10240
#define BBUF_OFF    (NSTAGE * STAGE_BYTES)
#define GEMM_SMEM   (2 * BBUF_OFF)

__global__ void __launch_bounds__(256, 2)
gemm_mma(const __nv_bfloat16* __restrict__ Ag, const __nv_bfloat16* __restrict__ Bg,
         float* __restrict__ Cg, int Nn, int Kfull, int Kper,
         int gridM, int gridN, int ntiles) {
    extern __shared__ char smraw[];
    const uint32_t sb = s2u(smraw);
    const int tid = threadIdx.x;
    const int lane = tid & 31, wid = tid >> 5;
    const int wm = wid & 1, wn = wid >> 1;
    const int nk = Kper >> 5;

    const int r = tid >> 1, half = tid & 1;
    const uint32_t dA = sb + r * 80 + half * 32;
    const uint32_t dB = sb + BBUF_OFF + r * 80 + half * 32;

    const uint32_t lrow = (uint32_t)(lane & 15);
    const uint32_t lcolb = (uint32_t)(lane >> 4) * 16;
    const uint32_t aLd = sb + (wm * 64 + lrow) * 80 + lcolb;
    const uint32_t bLd = sb + BBUF_OFF + (wn * 32 + lrow) * 80 + lcolb;

    for (int t = blockIdx.x; t < ntiles; t += gridDim.x) {
        int tm = t % gridM;
        int rem = t / gridM;
        int tn = rem % gridN;
        int z  = rem / gridN;
        const int bm = tm * 128, bn = tn * 128;
        const int koff = z * Kper;
        float* Cz = Cg + (size_t)z * (size_t)(gridM * 128) * Nn;

        const __nv_bfloat16* gA = Ag + (size_t)(bm + r) * Kfull + koff + half * 16;
        const __nv_bfloat16* gB = Bg + (size_t)(bn + r) * Kfull + koff + half * 16;

        float acc[4][4][4];
        #pragma unroll
        for (int i = 0; i < 4; i++)
            #pragma unroll
            for (int j = 0; j < 4; j++)
                #pragma unroll
                for (int q = 0; q < 4; q++) acc[i][j][q] = 0.f;

        #pragma unroll
        for (int s = 0; s < NSTAGE - 1; s++) {
            const __nv_bfloat16* a = gA + s * 32;
            const __nv_bfloat16* b = gB + s * 32;
            uint32_t so = (uint32_t)s * STAGE_BYTES;
            CPA16(dA + so, a); CPA16(dA + so + 16, a + 8);
            CPA16(dB + so, b); CPA16(dB + so + 16, b + 8);
            asm volatile("cp.async.commit_group;" ::: "memory");
        }

        for (int kt = 0; kt < nk; kt++) {
            asm volatile("cp.async.wait_group 2;" ::: "memory");
            __syncthreads();

            const uint32_t so = (uint32_t)(kt & (NSTAGE - 1)) * STAGE_BYTES;
            #pragma unroll
            for (int ks = 0; ks < 2; ks++) {
                uint32_t Ar[4][4], Br[2][4];
                #pragma unroll
                for (int mt = 0; mt < 4; mt++)
                    LDSM4(Ar[mt][0], Ar[mt][1], Ar[mt][2], Ar[mt][3],
                          aLd + so + mt * 1280 + ks * 32);
                #pragma unroll
                for (int p = 0; p < 2; p++)
                    LDSM4(Br[p][0], Br[p][1], Br[p][2], Br[p][3],
                          bLd + so + p * 1280 + ks * 32);
                #pragma unroll
                for (int mt = 0; mt < 4; mt++)
                    #pragma unroll
                    for (int nt = 0; nt < 4; nt++) {
                        uint32_t b0 = Br[nt >> 1][nt & 1];
                        uint32_t b1 = Br[nt >> 1][2 + (nt & 1)];
                        MMA16816(acc[mt][nt], Ar[mt], b0, b1);
                    }
            }

            int ls = kt + NSTAGE - 1;
            if (ls < nk) {
                uint32_t so2 = (uint32_t)(ls & (NSTAGE - 1)) * STAGE_BYTES;
                const __nv_bfloat16* a = gA + (size_t)ls * 32;
                const __nv_bfloat16* b = gB + (size_t)ls * 32;
                CPA16(dA + so2, a); CPA16(dA + so2 + 16, a + 8);
                CPA16(dB + so2, b); CPA16(dB + so2 + 16, b + 8);
            }
            asm volatile("cp.async.commit_group;" ::: "memory");
        }

        const int g = lane >> 2, t4 = lane & 3;
        #pragma unroll
        for (int mt = 0; mt < 4; mt++) {
            int row = bm + wm * 64 + mt * 16 + g;
            #pragma unroll
            for (int nt = 0; nt < 4; nt++) {
                int col = bn + wn * 32 + nt * 8 + 2 * t4;
                *(float2*)(Cz + (size_t)row * Nn + col)       = make_float2(acc[mt][nt][0], acc[mt][nt][1]);
                *(float2*)(Cz + (size_t)(row + 8) * Nn + col) = make_float2(acc[mt][nt][2], acc[mt][nt][3]);
            }
        }
        asm volatile("cp.async.wait_group 0;" ::: "memory");
        __syncthreads();
    }
}

// ---------------- router ----------------
__global__ void gate_kernel(const float* __restrict__ x,
                            const float* __restrict__ gw,
                            float* __restrict__ logits_out) {
    int n = blockIdx.x;
    int tid = threadIdx.x;
    __shared__ float sx[Dm];
    for (int i = tid; i < Dm; i += 256) sx[i] = x[(size_t)n * Dm + i];
    __syncthreads();
    int w = tid >> 5, lane = tid & 31;
    const float* g = gw + (size_t)w * Dm;
    float sum = 0.f;
    for (int d = lane; d < Dm; d += 32) sum += sx[d] * g[d];
    #pragma unroll
    for (int o = 16; o; o >>= 1) sum += __shfl_down_sync(0xffffffffu, sum, o);
    __shared__ float slog[Em];
    if (lane == 0) slog[w] = sum;
    __syncthreads();
    if (tid == 0) {
        float mx = slog[0];
        #pragma unroll
        for (int e = 1; e < Em; e++) mx = fmaxf(mx, slog[e]);
        float p[Em], Z = 0.f;
        #pragma unroll
        for (int e = 0; e < Em; e++) { p[e] = expf(slog[e] - mx); Z += p[e]; }
        #pragma unroll
        for (int e = 0; e < Em; e++) p[e] /= Z;
        int i0 = 0;
        #pragma unroll
        for (int e = 1; e < Em; e++) if (p[e] > p[i0]) i0 = e;
        int i1 = (i0 == 0) ? 1 : 0;
        #pragma unroll
        for (int e = 0; e < Em; e++) { if (e == i0 || e == i1) continue; if (p[e] > p[i1]) i1 = e; }
        float w0 = p[i0], w1 = p[i1], s = w0 + w1;
        g_topi[n * 2 + 0] = i0; g_topi[n * 2 + 1] = i1;
        g_topw[n * 2 + 0] = w0 / s; g_topw[n * 2 + 1] = w1 / s;
        #pragma unroll
        for (int e = 0; e < Em; e++) logits_out[(size_t)n * Em + e] = slog[e];
    }
}

// ---------------- deterministic per-expert token lists ----------------
__global__ void build_list_kernel() {
    int e = blockIdx.x;
    int tid = threadIdx.x;
    __shared__ int wcnt[8];
    __shared__ int base;
    if (tid == 0) base = 0;
    __syncthreads();
    for (int t0 = 0; t0 < Ntok; t0 += 256) {
        int n = t0 + tid;
        int k = -1;
        if (g_topi[2 * n] == e) k = 0;
        else if (g_topi[2 * n + 1] == e) k = 1;
        unsigned b = __ballot_sync(0xffffffffu, k >= 0);
        int lane = tid & 31, w = tid >> 5;
        if (lane == 0) wcnt[w] = __popc(b);
        __syncthreads();
        int off = base;
        for (int ww = 0; ww < w; ww++) off += wcnt[ww];
        off += __popc(b & ((1u << lane) - 1));
        if (k >= 0) g_elist[e * Ntok + off] = (uint32_t)n | ((uint32_t)k << 16);
        __syncthreads();
        if (tid == 0) {
            int tot = 0;
            for (int ww = 0; ww < 8; ww++) tot += wcnt[ww];
            base += tot;
        }
        __syncthreads();
    }
    if (tid == 0) g_ecnt[e] = base;
}

// ---------------- expert-major SwiGLU, warp-per-token, float4-vectorized ----------------
#define EFFN_SMEM (48 * FCH * 4)
__global__ void __launch_bounds__(256)
expert_ffn(const float* __restrict__ B1, const float* __restrict__ B3,
           const float* __restrict__ A2) {
    int e = blockIdx.x, ch = blockIdx.y;
    int f0 = ch * FCH;
    extern __shared__ float sm[];
    float* B1s = sm;                 // [rr][FCH]
    float* B3s = sm + 16 * FCH;
    float* A2s = sm + 32 * FCH;
    int tid = threadIdx.x, lane = tid & 31, wid = tid >> 5;

    {
        const float4* p1 = (const float4*)(B1 + ((size_t)e * Fm + f0 + tid) * 16);
        const float4* p3 = (const float4*)(B3 + ((size_t)e * Fm + f0 + tid) * 16);
        #pragma unroll
        for (int q = 0; q < 4; q++) {
            float4 v1 = p1[q], v3 = p3[q];
            B1s[(4*q+0)*FCH + tid] = v1.x; B1s[(4*q+1)*FCH + tid] = v1.y;
            B1s[(4*q+2)*FCH + tid] = v1.z; B1s[(4*q+3)*FCH + tid] = v1.w;
            B3s[(4*q+0)*FCH + tid] = v3.x; B3s[(4*q+1)*FCH + tid] = v3.y;
            B3s[(4*q+2)*FCH + tid] = v3.z; B3s[(4*q+3)*FCH + tid] = v3.w;
        }
        #pragma unroll
        for (int rr = 0; rr < 16; rr++)
            A2s[rr * FCH + tid] = A2[((size_t)e * 16 + rr) * Fm + f0 + tid];
    }
    __syncthreads();

    int cnt = g_ecnt[e];
    for (int i = wid; i < cnt; i += 8) {
        uint32_t pk = g_elist[e * Ntok + i];
        int n = pk & 0xFFFF, k = (int)(pk >> 16);
        size_t roff = (size_t)n * NBALL;
        float l13 = g_baseall[roff + 2 * Fm + e * 32 + lane];
        float l1r[16], l3r[16];
        #pragma unroll
        for (int rr = 0; rr < 16; rr++) {
            l1r[rr] = __shfl_sync(0xffffffffu, l13, rr);
            l3r[rr] = __shfl_sync(0xffffffffu, l13, 16 + rr);
        }
        float l2a[16];
        #pragma unroll
        for (int rr = 0; rr < 16; rr++) l2a[rr] = 0.f;

        const float* brow = g_baseall + roff;
        float* srow = g_s + ((size_t)n * 2 + k) * Fm;
        #pragma unroll
        for (int fi = 0; fi < 2; fi++) {
            int fb = fi * 128 + lane * 4;        // 4 consecutive f per lane
            float4 b1v = *(const float4*)(brow + f0 + fb);
            float4 b3v = *(const float4*)(brow + Fm + f0 + fb);
            float h1[4] = {0.f, 0.f, 0.f, 0.f};
            float h3[4] = {0.f, 0.f, 0.f, 0.f};
            #pragma unroll
            for (int rr = 0; rr < 16; rr++) {
                float4 w1 = *(const float4*)&B1s[rr * FCH + fb];
                float4 w3 = *(const float4*)&B3s[rr * FCH + fb];
                h1[0] = fmaf(l1r[rr], w1.x, h1[0]); h1[1] = fmaf(l1r[rr], w1.y, h1[1]);
                h1[2] = fmaf(l1r[rr], w1.z, h1[2]); h1[3] = fmaf(l1r[rr], w1.w, h1[3]);
                h3[0] = fmaf(l3r[rr], w3.x, h3[0]); h3[1] = fmaf(l3r[rr], w3.y, h3[1]);
                h3[2] = fmaf(l3r[rr], w3.z, h3[2]); h3[3] = fmaf(l3r[rr], w3.w, h3[3]);
            }
            float s4[4];
            float bb1[4] = {b1v.x, b1v.y, b1v.z, b1v.w};
            float bb3[4] = {b3v.x, b3v.y, b3v.z, b3v.w};
            #pragma unroll
            for (int j = 0; j < 4; j++) {
                float hh1 = fmaf(LSCALE, h1[j], bb1[j]);
                float hh3 = fmaf(LSCALE, h3[j], bb3[j]);
                float sig = 1.f / (1.f + expf(-hh1));
                s4[j] = hh1 * sig * hh3;
            }
            *(float4*)(srow + f0 + fb) = make_float4(s4[0], s4[1], s4[2], s4[3]);
            #pragma unroll
            for (int rr = 0; rr < 16; rr++) {
                float4 a2 = *(const float4*)&A2s[rr * FCH + fb];
                l2a[rr] = fmaf(s4[0], a2.x, fmaf(s4[1], a2.y, fmaf(s4[2], a2.z, fmaf(s4[3], a2.w, l2a[rr]))));
            }
        }
        #pragma unroll
        for (int rr = 0; rr < 16; rr++) {
            float v = l2a[rr];
            #pragma unroll
            for (int o = 16; o; o >>= 1) v += __shfl_down_sync(0xffffffffu, v, o);
            if (lane == 0)
                g_l2p[(((size_t)n * 2 + k) * NCH + ch) * 16 + rr] = v;
        }
    }
}

// ---------------- mix + bf16 split of smix (A-mode) ----------------
__global__ void mix_split_kernel() {
    int t = blockIdx.x * 256 + threadIdx.x;
    size_t idx = (size_t)t * 8;
    int n = (int)(idx / Fm);
    int f = (int)(idx - (size_t)n * Fm);
    float w0 = g_topw[2 * n], w1 = g_topw[2 * n + 1];
    const float* s0p = g_s + ((size_t)n * 2) * Fm + f;
    const float* s1p = g_s + ((size_t)n * 2 + 1) * Fm + f;
    float m[8];
    #pragma unroll
    for (int q = 0; q < 2; q++) {
        float4 a = *(const float4*)(s0p + 4 * q);
        float4 b = *(const float4*)(s1p + 4 * q);
        m[4*q+0] = w0 * a.x + w1 * b.x;
        m[4*q+1] = w0 * a.y + w1 * b.y;
        m[4*q+2] = w0 * a.z + w1 * b.z;
        m[4*q+3] = w0 * a.w + w1 * b.w;
    }
    uint4 H, L;
    split8(m, H, L);
    __nv_bfloat16* base = g_smc + (size_t)n * K3F + f;
    *(uint4*)base = H;
    *(uint4*)(base + Fm) = H;       // A-mode: hi, hi, lo
    *(uint4*)(base + 2 * Fm) = L;
}

// ---------------- output: split-K merge + LoRA ----------------
__global__ void lora_out_kernel(const float* __restrict__ B2, float* __restrict__ out) {
    int n = blockIdx.y;
    int d = blockIdx.x * 256 + threadIdx.x;
    __shared__ float sl2[32];
    __shared__ int se[2];
    if (threadIdx.x < 32) {
        int k = threadIdx.x >> 4, rr = threadIdx.x & 15;
        float v = 0.f;
        #pragma unroll
        for (int ch = 0; ch < NCH; ch++)
            v += g_l2p[(((size_t)n * 2 + k) * NCH + ch) * 16 + rr];
        sl2[threadIdx.x] = v * g_topw[n * 2 + k] * LSCALE;
    }
    if (threadIdx.x < 2) se[threadIdx.x] = g_topi[n * 2 + threadIdx.x];
    __syncthreads();
    float acc = 0.f;
    #pragma unroll
    for (int z = 0; z < ZW2; z++)
        acc += g_wpart[(size_t)z * Ntok * Dm + (size_t)n * Dm + d];
    #pragma unroll
    for (int k = 0; k < 2; k++) {
        int e = se[k];
        const float4* bp = (const float4*)(B2 + ((size_t)e * Dm + d) * Rm);
        #pragma unroll
        for (int q = 0; q < 4; q++) {
            float4 v = bp[q];
            acc += sl2[k*16+4*q+0]*v.x + sl2[k*16+4*q+1]*v.y + sl2[k*16+4*q+2]*v.z + sl2[k*16+4*q+3]*v.w;
        }
    }
    out[(size_t)n * Dm + d] = acc;
}

// --------------------------------- launch --------------------------------
extern "C" void kernel_launch(void* const* d_in, const int* in_sizes, int n_in,
                              void* d_out, int out_size) {
    const float* x      = (const float*)d_in[0];
    const float* gate_w = (const float*)d_in[1];
    const float* W1     = (const float*)d_in[2];
    const float* W3     = (const float*)d_in[3];
    const float* W2     = (const float*)d_in[4];
    const float* A1     = (const float*)d_in[5];
    const float* B1     = (const float*)d_in[6];
    const float* A3     = (const float*)d_in[7];
    const float* B3     = (const float*)d_in[8];
    const float* A2     = (const float*)d_in[9];
    const float* B2     = (const float*)d_in[10];

    float* out    = (float*)d_out;
    float* logits = (float*)d_out + (size_t)Ntok * Dm;

    float *baseall, *wpart;
    __nv_bfloat16 *xcat, *wallc, *w2c, *smc;
    cudaGetSymbolAddress((void**)&baseall, g_baseall);
    cudaGetSymbolAddress((void**)&wpart, g_wpart);
    cudaGetSymbolAddress((void**)&xcat,  g_xcat);
    cudaGetSymbolAddress((void**)&wallc, g_wallc);
    cudaGetSymbolAddress((void**)&w2c,   g_w2c);
    cudaGetSymbolAddress((void**)&smc,   g_smc);

    cudaFuncSetAttribute(gemm_mma, cudaFuncAttributeMaxDynamicSharedMemorySize, GEMM_SMEM);
    cudaFuncSetAttribute(expert_ffn, cudaFuncAttributeMaxDynamicSharedMemorySize, EFFN_SMEM);

    // splits
    split_kernel<<<Ntok * Dm / 8 / 256, 256>>>(x, xcat, Dm, Ntok * Dm / 8, 0);
    split_kernel<<<Fm * Dm / 8 / 256, 256>>>(W1, wallc, Dm, Fm * Dm / 8, 1);
    split_kernel<<<Fm * Dm / 8 / 256, 256>>>(W3, wallc + (size_t)Fm * K3D, Dm, Fm * Dm / 8, 1);
    split_a13_kernel<<<256 * Dm / 8 / 256, 256>>>(A1, A3, wallc + (size_t)2 * Fm * K3D);
    split_kernel<<<Dm * Fm / 8 / 256, 256>>>(W2, w2c, Fm, Dm * Fm / 8, 1);

    // router + expert lists
    gate_kernel<<<Ntok, 256>>>(x, gate_w, logits);
    build_list_kernel<<<Em, 256>>>();

    // fused base GEMM: [x@W1 | x@W3 | x@A13] — persistent
    {
        int ntiles = (Ntok / 128) * (NBALL / 128);      // 720
        gemm_mma<<<NPERSIST, 256, GEMM_SMEM>>>(xcat, wallc, baseall,
                                               NBALL, K3D, K3D,
                                               Ntok / 128, NBALL / 128, ntiles);
    }
    // expert-major SwiGLU + l2 partials (vectorized)
    {
        dim3 grid(Em, NCH);
        expert_ffn<<<grid, 256, EFFN_SMEM>>>(B1, B3, A2);
    }
    // mix + split
    mix_split_kernel<<<Ntok * Fm / 8 / 256, 256>>>();
    // down-projection GEMM, split-K=4: 512 tiles
    {
        int ntiles = (Ntok / 128) * (Dm / 128) * ZW2;   // 512
        gemm_mma<<<ntiles, 256, GEMM_SMEM>>>(smc, w2c, wpart,
                                             Dm, K3F, KPER_W2,
                                             Ntok / 128, Dm / 128, ntiles);
    }
    // merge partials + output LoRA
    {
        dim3 grid(Dm / 256, Ntok);
        lora_out_kernel<<<grid, 256>>>(B2, out);
    }
}

// round 13
// speedup vs baseline: 1.8724x; 1.0093x over previous
#include <cuda_runtime.h>
#include <cuda_bf16.h>
#include <math.h>
#include <stdint.h>

#define Ntok 1024
#define Dm   2048
#define Fm   5632
#define Em   8
#define Rm   16
#define LSCALE 2.0f
#define K3D  (3*Dm)    // 6144
#define K3F  (3*Fm)    // 16896
#define NBALL (2*Fm + 256)   // 11520
#define FCH  256
#define NCH  (Fm / FCH)      // 22
#define ZW2  2
#define KPER_W2 (K3F / ZW2)  // 8448
#define NPERSIST 592

// ---------------- device scratch ----------------
__device__ float g_baseall[(size_t)Ntok * NBALL];
__device__ float g_s    [(size_t)Ntok * 2 * Fm];
__device__ float g_l2p  [(size_t)Ntok * 2 * NCH * 16];
__device__ float g_wpart[(size_t)ZW2 * Ntok * Dm];
__device__ int   g_topi [Ntok * 2];
__device__ float g_topw [Ntok * 2];
__device__ uint32_t g_elist[Em * Ntok];
__device__ int   g_ecnt[Em];
__device__ __align__(256) __nv_bfloat16 g_xcat [(size_t)Ntok  * K3D];
__device__ __align__(256) __nv_bfloat16 g_wallc[(size_t)NBALL * K3D];
__device__ __align__(256) __nv_bfloat16 g_w2c  [(size_t)Dm    * K3F];
__device__ __align__(256) __nv_bfloat16 g_smc  [(size_t)Ntok  * K3F];

// ---------------- PTX helpers ----------------
__device__ __forceinline__ uint32_t s2u(const void* p) {
    uint32_t a;
    asm("{ .reg .u64 t; cvta.to.shared.u64 t, %1; cvt.u32.u64 %0, t; }" : "=r"(a) : "l"(p));
    return a;
}
#define CPA16(d, s) asm volatile("cp.async.cg.shared.global [%0], [%1], 16;" :: "r"(d), "l"(s))
#define LDSM4(R0,R1,R2,R3,addr) asm volatile( \
    "ldmatrix.sync.aligned.m8n8.x4.shared.b16 {%0,%1,%2,%3}, [%4];" \
    : "=r"(R0),"=r"(R1),"=r"(R2),"=r"(R3) : "r"(addr))
#define MMA16816(c, a, b0, b1) asm volatile( \
    "mma.sync.aligned.m16n8k16.row.col.f32.bf16.bf16.f32 " \
    "{%0,%1,%2,%3}, {%4,%5,%6,%7}, {%8,%9}, {%0,%1,%2,%3};" \
    : "+f"((c)[0]),"+f"((c)[1]),"+f"((c)[2]),"+f"((c)[3]) \
    : "r"((a)[0]),"r"((a)[1]),"r"((a)[2]),"r"((a)[3]), "r"(b0),"r"(b1))

// pack 8 fp32 -> (hi uint4, lo uint4) bf16
__device__ __forceinline__ void split8(const float* p, uint4& H, uint4& L) {
    float v[8];
    *(float4*)&v[0] = *(const float4*)p;
    *(float4*)&v[4] = *(const float4*)(p + 4);
    uint32_t h[4], l[4];
    #pragma unroll
    for (int i = 0; i < 4; i++) {
        __nv_bfloat16 h0 = __float2bfloat16(v[2*i]);
        __nv_bfloat16 h1 = __float2bfloat16(v[2*i+1]);
        __nv_bfloat16 l0 = __float2bfloat16(v[2*i]   - __bfloat162float(h0));
        __nv_bfloat16 l1 = __float2bfloat16(v[2*i+1] - __bfloat162float(h1));
        __nv_bfloat162 hp; hp.x = h0; hp.y = h1;
        __nv_bfloat162 lp; lp.x = l0; lp.y = l1;
        h[i] = *(uint32_t*)&hp;
        l[i] = *(uint32_t*)&lp;
    }
    H = make_uint4(h[0], h[1], h[2], h[3]);
    L = make_uint4(l[0], l[1], l[2], l[3]);
}

// ---------------- ONE fused split kernel (5 segments) ----------------
// blocks: [0,1024) x(A-mode) | [1024,6656) W1(B) | [6656,12288) W3(B)
//         | [12288,12544) A13(B) | [12544,18176) W2(B)
#define SPLIT_BLOCKS 18176
__global__ void split_all(const float* __restrict__ x,
                          const float* __restrict__ W1, const float* __restrict__ W3,
                          const float* __restrict__ A1, const float* __restrict__ A3,
                          const float* __restrict__ W2) {
    int b = blockIdx.x;
    int tid = threadIdx.x;
    if (b < 1024) {                       // x -> xcat, A-mode [hi|hi|lo], K=Dm
        int t = b * 256 + tid;
        size_t idx = (size_t)t * 8;
        int row = (int)(idx >> 11);       // /Dm
        int col = (int)(idx & (Dm - 1));
        uint4 H, L;
        split8(x + idx, H, L);
        __nv_bfloat16* base = g_xcat + (size_t)row * K3D + col;
        *(uint4*)base = H;
        *(uint4*)(base + Dm) = H;
        *(uint4*)(base + 2 * Dm) = L;
    } else if (b < 12288) {               // W1/W3 -> wallc, B-mode [hi|lo|hi], K=Dm
        int seg = (b < 6656) ? 0 : 1;
        int t = (b - (seg ? 6656 : 1024)) * 256 + tid;
        size_t idx = (size_t)t * 8;
        int row = (int)(idx >> 11);
        int col = (int)(idx & (Dm - 1));
        const float* src = (seg ? W3 : W1) + idx;
        uint4 H, L;
        split8(src, H, L);
        __nv_bfloat16* base = g_wallc + ((size_t)(seg ? Fm : 0) + row) * K3D + col;
        *(uint4*)base = H;
        *(uint4*)(base + Dm) = L;
        *(uint4*)(base + 2 * Dm) = H;
    } else if (b < 12544) {               // A13 -> wallc rows [2Fm..2Fm+256), B-mode
        int t = (b - 12288) * 256 + tid;
        size_t idx = (size_t)t * 8;
        int row = (int)(idx >> 11);
        int col = (int)(idx & (Dm - 1));
        int e = row >> 5, rr = row & 31;
        const float* src = (rr < 16) ? (A1 + ((size_t)e * 16 + rr) * Dm)
                                     : (A3 + ((size_t)e * 16 + (rr - 16)) * Dm);
        uint4 H, L;
        split8(src + col, H, L);
        __nv_bfloat16* base = g_wallc + ((size_t)2 * Fm + row) * K3D + col;
        *(uint4*)base = H;
        *(uint4*)(base + Dm) = L;
        *(uint4*)(base + 2 * Dm) = H;
    } else {                              // W2 -> w2c, B-mode, K=Fm
        int t = (b - 12544) * 256 + tid;
        size_t idx = (size_t)t * 8;
        int row = (int)(idx / Fm);
        int col = (int)(idx - (size_t)row * Fm);
        uint4 H, L;
        split8(W2 + idx, H, L);
        __nv_bfloat16* base = g_w2c + (size_t)row * K3F + col;
        *(uint4*)base = H;
        *(uint4*)(base + Fm) = L;
        *(uint4*)(base + 2 * Fm) = H;
    }
}

// ======== persistent HMMA GEMM (R7 config): 128x128, warp 64x32, BK=32, 4-stage ========
#define NSTAGE      4
#define STAGE_BYTES 10240
#define BBUF_OFF    (NSTAGE * STAGE_BYTES)
#define GEMM_SMEM   (2 * BBUF_OFF)

__global__ void __launch_bounds__(256, 2)
gemm_mma(const __nv_bfloat16* __restrict__ Ag, const __nv_bfloat16* __restrict__ Bg,
         float* __restrict__ Cg, int Nn, int Kfull, int Kper,
         int gridM, int gridN, int ntiles) {
    extern __shared__ char smraw[];
    const uint32_t sb = s2u(smraw);
    const int tid = threadIdx.x;
    const int lane = tid & 31, wid = tid >> 5;
    const int wm = wid & 1, wn = wid >> 1;
    const int nk = Kper >> 5;

    const int r = tid >> 1, half = tid & 1;
    const uint32_t dA = sb + r * 80 + half * 32;
    const uint32_t dB = sb + BBUF_OFF + r * 80 + half * 32;

    const uint32_t lrow = (uint32_t)(lane & 15);
    const uint32_t lcolb = (uint32_t)(lane >> 4) * 16;
    const uint32_t aLd = sb + (wm * 64 + lrow) * 80 + lcolb;
    const uint32_t bLd = sb + BBUF_OFF + (wn * 32 + lrow) * 80 + lcolb;

    for (int t = blockIdx.x; t < ntiles; t += gridDim.x) {
        int tm = t % gridM;
        int rem = t / gridM;
        int tn = rem % gridN;
        int z  = rem / gridN;
        const int bm = tm * 128, bn = tn * 128;
        const int koff = z * Kper;
        float* Cz = Cg + (size_t)z * (size_t)(gridM * 128) * Nn;

        const __nv_bfloat16* gA = Ag + (size_t)(bm + r) * Kfull + koff + half * 16;
        const __nv_bfloat16* gB = Bg + (size_t)(bn + r) * Kfull + koff + half * 16;

        float acc[4][4][4];
        #pragma unroll
        for (int i = 0; i < 4; i++)
            #pragma unroll
            for (int j = 0; j < 4; j++)
                #pragma unroll
                for (int q = 0; q < 4; q++) acc[i][j][q] = 0.f;

        #pragma unroll
        for (int s = 0; s < NSTAGE - 1; s++) {
            const __nv_bfloat16* a = gA + s * 32;
            const __nv_bfloat16* b = gB + s * 32;
            uint32_t so = (uint32_t)s * STAGE_BYTES;
            CPA16(dA + so, a); CPA16(dA + so + 16, a + 8);
            CPA16(dB + so, b); CPA16(dB + so + 16, b + 8);
            asm volatile("cp.async.commit_group;" ::: "memory");
        }

        for (int kt = 0; kt < nk; kt++) {
            asm volatile("cp.async.wait_group 2;" ::: "memory");
            __syncthreads();

            const uint32_t so = (uint32_t)(kt & (NSTAGE - 1)) * STAGE_BYTES;
            #pragma unroll
            for (int ks = 0; ks < 2; ks++) {
                uint32_t Ar[4][4], Br[2][4];
                #pragma unroll
                for (int mt = 0; mt < 4; mt++)
                    LDSM4(Ar[mt][0], Ar[mt][1], Ar[mt][2], Ar[mt][3],
                          aLd + so + mt * 1280 + ks * 32);
                #pragma unroll
                for (int p = 0; p < 2; p++)
                    LDSM4(Br[p][0], Br[p][1], Br[p][2], Br[p][3],
                          bLd + so + p * 1280 + ks * 32);
                #pragma unroll
                for (int mt = 0; mt < 4; mt++)
                    #pragma unroll
                    for (int nt = 0; nt < 4; nt++) {
                        uint32_t b0 = Br[nt >> 1][nt & 1];
                        uint32_t b1 = Br[nt >> 1][2 + (nt & 1)];
                        MMA16816(acc[mt][nt], Ar[mt], b0, b1);
                    }
            }

            int ls = kt + NSTAGE - 1;
            if (ls < nk) {
                uint32_t so2 = (uint32_t)(ls & (NSTAGE - 1)) * STAGE_BYTES;
                const __nv_bfloat16* a = gA + (size_t)ls * 32;
                const __nv_bfloat16* b = gB + (size_t)ls * 32;
                CPA16(dA + so2, a); CPA16(dA + so2 + 16, a + 8);
                CPA16(dB + so2, b); CPA16(dB + so2 + 16, b + 8);
            }
            asm volatile("cp.async.commit_group;" ::: "memory");
        }

        const int g = lane >> 2, t4 = lane & 3;
        #pragma unroll
        for (int mt = 0; mt < 4; mt++) {
            int row = bm + wm * 64 + mt * 16 + g;
            #pragma unroll
            for (int nt = 0; nt < 4; nt++) {
                int col = bn + wn * 32 + nt * 8 + 2 * t4;
                *(float2*)(Cz + (size_t)row * Nn + col)       = make_float2(acc[mt][nt][0], acc[mt][nt][1]);
                *(float2*)(Cz + (size_t)(row + 8) * Nn + col) = make_float2(acc[mt][nt][2], acc[mt][nt][3]);
            }
        }
        asm volatile("cp.async.wait_group 0;" ::: "memory");
        __syncthreads();
    }
}

// ---------------- router ----------------
__global__ void gate_kernel(const float* __restrict__ x,
                            const float* __restrict__ gw,
                            float* __restrict__ logits_out) {
    int n = blockIdx.x;
    int tid = threadIdx.x;
    __shared__ float sx[Dm];
    for (int i = tid; i < Dm; i += 256) sx[i] = x[(size_t)n * Dm + i];
    __syncthreads();
    int w = tid >> 5, lane = tid & 31;
    const float* g = gw + (size_t)w * Dm;
    float sum = 0.f;
    for (int d = lane; d < Dm; d += 32) sum += sx[d] * g[d];
    #pragma unroll
    for (int o = 16; o; o >>= 1) sum += __shfl_down_sync(0xffffffffu, sum, o);
    __shared__ float slog[Em];
    if (lane == 0) slog[w] = sum;
    __syncthreads();
    if (tid == 0) {
        float mx = slog[0];
        #pragma unroll
        for (int e = 1; e < Em; e++) mx = fmaxf(mx, slog[e]);
        float p[Em], Z = 0.f;
        #pragma unroll
        for (int e = 0; e < Em; e++) { p[e] = expf(slog[e] - mx); Z += p[e]; }
        #pragma unroll
        for (int e = 0; e < Em; e++) p[e] /= Z;
        int i0 = 0;
        #pragma unroll
        for (int e = 1; e < Em; e++) if (p[e] > p[i0]) i0 = e;
        int i1 = (i0 == 0) ? 1 : 0;
        #pragma unroll
        for (int e = 0; e < Em; e++) { if (e == i0 || e == i1) continue; if (p[e] > p[i1]) i1 = e; }
        float w0 = p[i0], w1 = p[i1], s = w0 + w1;
        g_topi[n * 2 + 0] = i0; g_topi[n * 2 + 1] = i1;
        g_topw[n * 2 + 0] = w0 / s; g_topw[n * 2 + 1] = w1 / s;
        #pragma unroll
        for (int e = 0; e < Em; e++) logits_out[(size_t)n * Em + e] = slog[e];
    }
}

// ---------------- deterministic per-expert token lists ----------------
__global__ void build_list_kernel() {
    int e = blockIdx.x;
    int tid = threadIdx.x;
    __shared__ int wcnt[8];
    __shared__ int base;
    if (tid == 0) base = 0;
    __syncthreads();
    for (int t0 = 0; t0 < Ntok; t0 += 256) {
        int n = t0 + tid;
        int k = -1;
        if (g_topi[2 * n] == e) k = 0;
        else if (g_topi[2 * n + 1] == e) k = 1;
        unsigned b = __ballot_sync(0xffffffffu, k >= 0);
        int lane = tid & 31, w = tid >> 5;
        if (lane == 0) wcnt[w] = __popc(b);
        __syncthreads();
        int off = base;
        for (int ww = 0; ww < w; ww++) off += wcnt[ww];
        off += __popc(b & ((1u << lane) - 1));
        if (k >= 0) g_elist[e * Ntok + off] = (uint32_t)n | ((uint32_t)k << 16);
        __syncthreads();
        if (tid == 0) {
            int tot = 0;
            for (int ww = 0; ww < 8; ww++) tot += wcnt[ww];
            base += tot;
        }
        __syncthreads();
    }
    if (tid == 0) g_ecnt[e] = base;
}

// ---------------- expert-major SwiGLU, warp-per-token, float4-vectorized ----------------
#define EFFN_SMEM (48 * FCH * 4)
__global__ void __launch_bounds__(256)
expert_ffn(const float* __restrict__ B1, const float* __restrict__ B3,
           const float* __restrict__ A2) {
    int e = blockIdx.x, ch = blockIdx.y;
    int f0 = ch * FCH;
    extern __shared__ float sm[];
    float* B1s = sm;
    float* B3s = sm + 16 * FCH;
    float* A2s = sm + 32 * FCH;
    int tid = threadIdx.x, lane = tid & 31, wid = tid >> 5;

    {
        const float4* p1 = (const float4*)(B1 + ((size_t)e * Fm + f0 + tid) * 16);
        const float4* p3 = (const float4*)(B3 + ((size_t)e * Fm + f0 + tid) * 16);
        #pragma unroll
        for (int q = 0; q < 4; q++) {
            float4 v1 = p1[q], v3 = p3[q];
            B1s[(4*q+0)*FCH + tid] = v1.x; B1s[(4*q+1)*FCH + tid] = v1.y;
            B1s[(4*q+2)*FCH + tid] = v1.z; B1s[(4*q+3)*FCH + tid] = v1.w;
            B3s[(4*q+0)*FCH + tid] = v3.x; B3s[(4*q+1)*FCH + tid] = v3.y;
            B3s[(4*q+2)*FCH + tid] = v3.z; B3s[(4*q+3)*FCH + tid] = v3.w;
        }
        #pragma unroll
        for (int rr = 0; rr < 16; rr++)
            A2s[rr * FCH + tid] = A2[((size_t)e * 16 + rr) * Fm + f0 + tid];
    }
    __syncthreads();

    int cnt = g_ecnt[e];
    for (int i = wid; i < cnt; i += 8) {
        uint32_t pk = g_elist[e * Ntok + i];
        int n = pk & 0xFFFF, k = (int)(pk >> 16);
        size_t roff = (size_t)n * NBALL;
        float l13 = g_baseall[roff + 2 * Fm + e * 32 + lane];
        float l1r[16], l3r[16];
        #pragma unroll
        for (int rr = 0; rr < 16; rr++) {
            l1r[rr] = __shfl_sync(0xffffffffu, l13, rr);
            l3r[rr] = __shfl_sync(0xffffffffu, l13, 16 + rr);
        }
        float l2a[16];
        #pragma unroll
        for (int rr = 0; rr < 16; rr++) l2a[rr] = 0.f;

        const float* brow = g_baseall + roff;
        float* srow = g_s + ((size_t)n * 2 + k) * Fm;
        #pragma unroll
        for (int fi = 0; fi < 2; fi++) {
            int fb = fi * 128 + lane * 4;
            float4 b1v = *(const float4*)(brow + f0 + fb);
            float4 b3v = *(const float4*)(brow + Fm + f0 + fb);
            float h1[4] = {0.f, 0.f, 0.f, 0.f};
            float h3[4] = {0.f, 0.f, 0.f, 0.f};
            #pragma unroll
            for (int rr = 0; rr < 16; rr++) {
                float4 w1 = *(const float4*)&B1s[rr * FCH + fb];
                float4 w3 = *(const float4*)&B3s[rr * FCH + fb];
                h1[0] = fmaf(l1r[rr], w1.x, h1[0]); h1[1] = fmaf(l1r[rr], w1.y, h1[1]);
                h1[2] = fmaf(l1r[rr], w1.z, h1[2]); h1[3] = fmaf(l1r[rr], w1.w, h1[3]);
                h3[0] = fmaf(l3r[rr], w3.x, h3[0]); h3[1] = fmaf(l3r[rr], w3.y, h3[1]);
                h3[2] = fmaf(l3r[rr], w3.z, h3[2]); h3[3] = fmaf(l3r[rr], w3.w, h3[3]);
            }
            float s4[4];
            float bb1[4] = {b1v.x, b1v.y, b1v.z, b1v.w};
            float bb3[4] = {b3v.x, b3v.y, b3v.z, b3v.w};
            #pragma unroll
            for (int j = 0; j < 4; j++) {
                float hh1 = fmaf(LSCALE, h1[j], bb1[j]);
                float hh3 = fmaf(LSCALE, h3[j], bb3[j]);
                float sig = 1.f / (1.f + expf(-hh1));
                s4[j] = hh1 * sig * hh3;
            }
            *(float4*)(srow + f0 + fb) = make_float4(s4[0], s4[1], s4[2], s4[3]);
            #pragma unroll
            for (int rr = 0; rr < 16; rr++) {
                float4 a2 = *(const float4*)&A2s[rr * FCH + fb];
                l2a[rr] = fmaf(s4[0], a2.x, fmaf(s4[1], a2.y, fmaf(s4[2], a2.z, fmaf(s4[3], a2.w, l2a[rr]))));
            }
        }
        #pragma unroll
        for (int rr = 0; rr < 16; rr++) {
            float v = l2a[rr];
            #pragma unroll
            for (int o = 16; o; o >>= 1) v += __shfl_down_sync(0xffffffffu, v, o);
            if (lane == 0)
                g_l2p[(((size_t)n * 2 + k) * NCH + ch) * 16 + rr] = v;
        }
    }
}

// ---------------- mix + bf16 split of smix (A-mode) ----------------
__global__ void mix_split_kernel() {
    int t = blockIdx.x * 256 + threadIdx.x;
    size_t idx = (size_t)t * 8;
    int n = (int)(idx / Fm);
    int f = (int)(idx - (size_t)n * Fm);
    float w0 = g_topw[2 * n], w1 = g_topw[2 * n + 1];
    const float* s0p = g_s + ((size_t)n * 2) * Fm + f;
    const float* s1p = g_s + ((size_t)n * 2 + 1) * Fm + f;
    float m[8];
    #pragma unroll
    for (int q = 0; q < 2; q++) {
        float4 a = *(const float4*)(s0p + 4 * q);
        float4 b = *(const float4*)(s1p + 4 * q);
        m[4*q+0] = w0 * a.x + w1 * b.x;
        m[4*q+1] = w0 * a.y + w1 * b.y;
        m[4*q+2] = w0 * a.z + w1 * b.z;
        m[4*q+3] = w0 * a.w + w1 * b.w;
    }
    uint4 H, L;
    split8(m, H, L);
    __nv_bfloat16* base = g_smc + (size_t)n * K3F + f;
    *(uint4*)base = H;
    *(uint4*)(base + Fm) = H;       // A-mode: hi, hi, lo
    *(uint4*)(base + 2 * Fm) = L;
}

// ---------------- output: split-K merge + LoRA ----------------
__global__ void lora_out_kernel(const float* __restrict__ B2, float* __restrict__ out) {
    int n = blockIdx.y;
    int d = blockIdx.x * 256 + threadIdx.x;
    __shared__ float sl2[32];
    __shared__ int se[2];
    if (threadIdx.x < 32) {
        int k = threadIdx.x >> 4, rr = threadIdx.x & 15;
        float v = 0.f;
        #pragma unroll
        for (int ch = 0; ch < NCH; ch++)
            v += g_l2p[(((size_t)n * 2 + k) * NCH + ch) * 16 + rr];
        sl2[threadIdx.x] = v * g_topw[n * 2 + k] * LSCALE;
    }
    if (threadIdx.x < 2) se[threadIdx.x] = g_topi[n * 2 + threadIdx.x];
    __syncthreads();
    float acc = 0.f;
    #pragma unroll
    for (int z = 0; z < ZW2; z++)
        acc += g_wpart[(size_t)z * Ntok * Dm + (size_t)n * Dm + d];
    #pragma unroll
    for (int k = 0; k < 2; k++) {
        int e = se[k];
        const float4* bp = (const float4*)(B2 + ((size_t)e * Dm + d) * Rm);
        #pragma unroll
        for (int q = 0; q < 4; q++) {
            float4 v = bp[q];
            acc += sl2[k*16+4*q+0]*v.x + sl2[k*16+4*q+1]*v.y + sl2[k*16+4*q+2]*v.z + sl2[k*16+4*q+3]*v.w;
        }
    }
    out[(size_t)n * Dm + d] = acc;
}

// --------------------------------- launch --------------------------------
extern "C" void kernel_launch(void* const* d_in, const int* in_sizes, int n_in,
                              void* d_out, int out_size) {
    const float* x      = (const float*)d_in[0];
    const float* gate_w = (const float*)d_in[1];
    const float* W1     = (const float*)d_in[2];
    const float* W3     = (const float*)d_in[3];
    const float* W2     = (const float*)d_in[4];
    const float* A1     = (const float*)d_in[5];
    const float* B1     = (const float*)d_in[6];
    const float* A3     = (const float*)d_in[7];
    const float* B3     = (const float*)d_in[8];
    const float* A2     = (const float*)d_in[9];
    const float* B2     = (const float*)d_in[10];

    float* out    = (float*)d_out;
    float* logits = (float*)d_out + (size_t)Ntok * Dm;

    float *baseall, *wpart;
    __nv_bfloat16 *xcat, *wallc, *w2c, *smc;
    cudaGetSymbolAddress((void**)&baseall, g_baseall);
    cudaGetSymbolAddress((void**)&wpart, g_wpart);
    cudaGetSymbolAddress((void**)&xcat,  g_xcat);
    cudaGetSymbolAddress((void**)&wallc, g_wallc);
    cudaGetSymbolAddress((void**)&w2c,   g_w2c);
    cudaGetSymbolAddress((void**)&smc,   g_smc);

    cudaFuncSetAttribute(gemm_mma, cudaFuncAttributeMaxDynamicSharedMemorySize, GEMM_SMEM);
    cudaFuncSetAttribute(expert_ffn, cudaFuncAttributeMaxDynamicSharedMemorySize, EFFN_SMEM);

    // one fused split launch (x, W1, W3, A13, W2)
    split_all<<<SPLIT_BLOCKS, 256>>>(x, W1, W3, A1, A3, W2);

    // router + expert lists
    gate_kernel<<<Ntok, 256>>>(x, gate_w, logits);
    build_list_kernel<<<Em, 256>>>();

    // fused base GEMM: [x@W1 | x@W3 | x@A13] — persistent
    {
        int ntiles = (Ntok / 128) * (NBALL / 128);      // 720
        gemm_mma<<<NPERSIST, 256, GEMM_SMEM>>>(xcat, wallc, baseall,
                                               NBALL, K3D, K3D,
                                               Ntok / 128, NBALL / 128, ntiles);
    }
    // expert-major SwiGLU + l2 partials (vectorized)
    {
        dim3 grid(Em, NCH);
        expert_ffn<<<grid, 256, EFFN_SMEM>>>(B1, B3, A2);
    }
    // mix + split
    mix_split_kernel<<<Ntok * Fm / 8 / 256, 256>>>();
    // down-projection GEMM, split-K=2: 256 tiles, one co-resident wave
    {
        int ntiles = (Ntok / 128) * (Dm / 128) * ZW2;   // 256
        gemm_mma<<<ntiles, 256, GEMM_SMEM>>>(smc, w2c, wpart,
                                             Dm, K3F, KPER_W2,
                                             Ntok / 128, Dm / 128, ntiles);
    }
    // merge partials + output LoRA
    {
        dim3 grid(Dm / 256, Ntok);
        lora_out_kernel<<<grid, 256>>>(B2, out);
    }
}